// round 1
// baseline (speedup 1.0000x reference)
#include <cuda_runtime.h>
#include <math.h>

#define M_ROWS 32768          // B*N
#define NB 32
#define NNODE 1024

// ---------------- scratch (device globals, allocation-free) ----------------
__device__ float g_thsm[6];
__device__ float g_Q[2u * 1024u * 1024u];          // mixed transition Q[2][N][N]
__device__ float g_hp [(size_t)M_ROWS * 128];      // h_prime
__device__ float g_h  [(size_t)M_ROWS * 128];      // diffusion output
__device__ float g_z  [(size_t)M_ROWS * 128];      // diffusion pre-linear
__device__ float g_x  [(size_t)M_ROWS * 256];      // concat buffer
__device__ float g_qb [(size_t)M_ROWS * 128];
__device__ float g_kb [(size_t)M_ROWS * 128];
__device__ float g_vb [(size_t)M_ROWS * 128];
__device__ float g_ctx[(size_t)M_ROWS * 128];

// ---------------- theta softmax (K=3, 2 layers) ----------------
__global__ void theta_softmax_kernel(const float* __restrict__ th) {
    int l = threadIdx.x;
    if (l < 2) {
        float a = th[l*3+0], b = th[l*3+1], c = th[l*3+2];
        float m = fmaxf(a, fmaxf(b, c));
        float ea = expf(a - m), eb = expf(b - m), ec = expf(c - m);
        float s = ea + eb + ec;
        g_thsm[l*3+0] = ea / s;
        g_thsm[l*3+1] = eb / s;
        g_thsm[l*3+2] = ec / s;
    }
}

// ---------------- Q[l] = sum_k thsm[l,k] * T[l,k] ----------------
__global__ void qmix_kernel(const float* __restrict__ T) {
    size_t i = (size_t)blockIdx.x * 256 + threadIdx.x;   // < 2*1048576
    size_t l  = i >> 20;
    size_t ij = i & 1048575u;
    const float* Tl = T + l * 3u * 1048576u;
    g_Q[i] = g_thsm[l*3+0] * Tl[ij]
           + g_thsm[l*3+1] * Tl[1048576u + ij]
           + g_thsm[l*3+2] * Tl[2u*1048576u + ij];
}

// ---------------- generic SGEMM: C = [base +] act(A@W + bias) ----------------
// A[M,K] row-major, W[K,N], C[M,N]; M%64==0, N%64==0, K%16==0
__global__ __launch_bounds__(256) void sgemm_kernel(
    const float* __restrict__ A, const float* __restrict__ W,
    const float* __restrict__ bias, const float* __restrict__ base,
    float* __restrict__ C, int M, int K, int N, int relu)
{
    __shared__ float As[64][17];
    __shared__ __align__(16) float Ws[16][64];
    const int tid = threadIdx.x;
    const int tx = tid & 15, ty = tid >> 4;
    const int row0 = blockIdx.y << 6;
    const int col0 = blockIdx.x << 6;
    const int ar = tid >> 2, ac = (tid & 3) << 2;   // A tile: 64x16
    const int wr = tid >> 4, wc = (tid & 15) << 2;  // W tile: 16x64

    float acc[4][4];
#pragma unroll
    for (int i = 0; i < 4; i++)
#pragma unroll
        for (int j = 0; j < 4; j++) acc[i][j] = 0.f;

    for (int k0 = 0; k0 < K; k0 += 16) {
        float4 av = *reinterpret_cast<const float4*>(A + (size_t)(row0 + ar) * K + k0 + ac);
        float4 wv = *reinterpret_cast<const float4*>(W + (size_t)(k0 + wr) * N + col0 + wc);
        __syncthreads();
        As[ar][ac+0] = av.x; As[ar][ac+1] = av.y; As[ar][ac+2] = av.z; As[ar][ac+3] = av.w;
        *reinterpret_cast<float4*>(&Ws[wr][wc]) = wv;
        __syncthreads();
#pragma unroll
        for (int kk = 0; kk < 16; ++kk) {
            float a0 = As[ty*4+0][kk], a1 = As[ty*4+1][kk];
            float a2 = As[ty*4+2][kk], a3 = As[ty*4+3][kk];
            float4 bv = *reinterpret_cast<const float4*>(&Ws[kk][tx*4]);
            acc[0][0] += a0*bv.x; acc[0][1] += a0*bv.y; acc[0][2] += a0*bv.z; acc[0][3] += a0*bv.w;
            acc[1][0] += a1*bv.x; acc[1][1] += a1*bv.y; acc[1][2] += a1*bv.z; acc[1][3] += a1*bv.w;
            acc[2][0] += a2*bv.x; acc[2][1] += a2*bv.y; acc[2][2] += a2*bv.z; acc[2][3] += a2*bv.w;
            acc[3][0] += a3*bv.x; acc[3][1] += a3*bv.y; acc[3][2] += a3*bv.z; acc[3][3] += a3*bv.w;
        }
    }
#pragma unroll
    for (int i = 0; i < 4; i++) {
        int r = row0 + ty*4 + i;
#pragma unroll
        for (int j = 0; j < 4; j++) {
            int c = col0 + tx*4 + j;
            float v = acc[i][j] + bias[c];
            if (relu) v = fmaxf(v, 0.f);
            if (base) v += base[(size_t)r * N + c];
            C[(size_t)r * N + c] = v;
        }
    }
}

// -------- masked diffusion GEMM: Z[b] = (Qm ⊙ Adj[b]) @ Hin[b], Hin/Z [B,N,F] --------
__global__ __launch_bounds__(256) void diff_gemm_kernel(
    const float* __restrict__ Qm, const float* __restrict__ Adj,
    const float* __restrict__ Hin, float* __restrict__ Z, int F)
{
    __shared__ float Ps[64][17];
    __shared__ __align__(16) float Hs[16][64];
    const int tid = threadIdx.x;
    const int tx = tid & 15, ty = tid >> 4;
    const int b  = blockIdx.z;
    const int i0 = blockIdx.y << 6;
    const int f0 = blockIdx.x << 6;
    const int ar = tid >> 2, ac = (tid & 3) << 2;
    const int wr = tid >> 4, wc = (tid & 15) << 2;
    const size_t adjb = (size_t)b * NNODE * NNODE;
    const size_t hb   = (size_t)b * NNODE * F;

    float acc[4][4];
#pragma unroll
    for (int i = 0; i < 4; i++)
#pragma unroll
        for (int j = 0; j < 4; j++) acc[i][j] = 0.f;

    for (int j0 = 0; j0 < NNODE; j0 += 16) {
        size_t qoff = (size_t)(i0 + ar) * NNODE + j0 + ac;
        float4 qv = *reinterpret_cast<const float4*>(Qm + qoff);
        float4 av = *reinterpret_cast<const float4*>(Adj + adjb + qoff);
        float4 hv = *reinterpret_cast<const float4*>(Hin + hb + (size_t)(j0 + wr) * F + f0 + wc);
        __syncthreads();
        Ps[ar][ac+0] = qv.x * av.x; Ps[ar][ac+1] = qv.y * av.y;
        Ps[ar][ac+2] = qv.z * av.z; Ps[ar][ac+3] = qv.w * av.w;
        *reinterpret_cast<float4*>(&Hs[wr][wc]) = hv;
        __syncthreads();
#pragma unroll
        for (int kk = 0; kk < 16; ++kk) {
            float a0 = Ps[ty*4+0][kk], a1 = Ps[ty*4+1][kk];
            float a2 = Ps[ty*4+2][kk], a3 = Ps[ty*4+3][kk];
            float4 bv = *reinterpret_cast<const float4*>(&Hs[kk][tx*4]);
            acc[0][0] += a0*bv.x; acc[0][1] += a0*bv.y; acc[0][2] += a0*bv.z; acc[0][3] += a0*bv.w;
            acc[1][0] += a1*bv.x; acc[1][1] += a1*bv.y; acc[1][2] += a1*bv.z; acc[1][3] += a1*bv.w;
            acc[2][0] += a2*bv.x; acc[2][1] += a2*bv.y; acc[2][2] += a2*bv.z; acc[2][3] += a2*bv.w;
            acc[3][0] += a3*bv.x; acc[3][1] += a3*bv.y; acc[3][2] += a3*bv.z; acc[3][3] += a3*bv.w;
        }
    }
#pragma unroll
    for (int i = 0; i < 4; i++) {
        int r = i0 + ty*4 + i;
#pragma unroll
        for (int j = 0; j < 4; j++) {
            int c = f0 + tx*4 + j;
            Z[hb + (size_t)r * F + c] = acc[i][j];
        }
    }
}

// ---------------- flash attention: H=2 heads, d=64, N=1024 ----------------
// grid (N/64, H, B); 64 threads = 1 thread per query row
__global__ __launch_bounds__(64) void attn_kernel(
    const float* __restrict__ Q, const float* __restrict__ K,
    const float* __restrict__ V, float* __restrict__ O)
{
    extern __shared__ __align__(16) float sm[];
    float* Ks = sm;                  // [64][68]
    float* Vs = sm + 64 * 68;        // [64][68]
    float* Ss = sm + 2 * 64 * 68;    // [64][65]
    const int tid = threadIdx.x;
    const int b = blockIdx.z, h = blockIdx.y;
    const int q0 = blockIdx.x * 64;
    const size_t rb = (size_t)b * NNODE;
    const int hoff = h * 64;

    // stage Q tile (coalesced) then pull this thread's query into registers
    for (int it = 0; it < 64; ++it)
        Ks[it * 68 + tid] = Q[(rb + q0 + it) * 128 + hoff + tid];
    __syncthreads();
    float qreg[64];
#pragma unroll
    for (int d = 0; d < 64; ++d) qreg[d] = Ks[tid * 68 + d] * 0.125f;  // 1/sqrt(64)

    float m = -1e30f, l = 0.f;
    float acc[64];
#pragma unroll
    for (int d = 0; d < 64; ++d) acc[d] = 0.f;

    for (int j0 = 0; j0 < NNODE; j0 += 64) {
        __syncthreads();
        for (int it = 0; it < 64; ++it) {
            Ks[it * 68 + tid] = K[(rb + j0 + it) * 128 + hoff + tid];
            Vs[it * 68 + tid] = V[(rb + j0 + it) * 128 + hoff + tid];
        }
        __syncthreads();

        float tmax = -1e30f;
        for (int j = 0; j < 64; ++j) {
            const float4* kr = reinterpret_cast<const float4*>(Ks + j * 68);
            float s0 = 0.f, s1 = 0.f, s2 = 0.f, s3 = 0.f;
#pragma unroll
            for (int d4 = 0; d4 < 16; ++d4) {
                float4 kv = kr[d4];
                s0 += qreg[d4*4+0] * kv.x;
                s1 += qreg[d4*4+1] * kv.y;
                s2 += qreg[d4*4+2] * kv.z;
                s3 += qreg[d4*4+3] * kv.w;
            }
            float s = (s0 + s1) + (s2 + s3);
            Ss[tid * 65 + j] = s;
            tmax = fmaxf(tmax, s);
        }
        float mt = fmaxf(m, tmax);
        float corr = __expf(m - mt);
        l *= corr;
#pragma unroll
        for (int d = 0; d < 64; ++d) acc[d] *= corr;
        for (int j = 0; j < 64; ++j) {
            float p = __expf(Ss[tid * 65 + j] - mt);
            l += p;
            const float4* vr = reinterpret_cast<const float4*>(Vs + j * 68);
#pragma unroll
            for (int d4 = 0; d4 < 16; ++d4) {
                float4 vv = vr[d4];
                acc[d4*4+0] += p * vv.x;
                acc[d4*4+1] += p * vv.y;
                acc[d4*4+2] += p * vv.z;
                acc[d4*4+3] += p * vv.w;
            }
        }
        m = mt;
    }
    float inv = 1.f / l;
#pragma unroll
    for (int d = 0; d < 64; ++d)
        O[(rb + q0 + tid) * 128 + hoff + d] = acc[d] * inv;
}

// ---------------- concat [h | hp] -> x ----------------
__global__ void concat_kernel(const float* __restrict__ a, const float* __restrict__ b,
                              float* __restrict__ o) {
    size_t i = (size_t)blockIdx.x * 256 + threadIdx.x;   // < M_ROWS*256
    size_t row = i >> 8;
    int c = (int)(i & 255u);
    o[i] = (c < 128) ? a[row * 128 + c] : b[row * 128 + (c - 128)];
}

// ---------------- final classifier: out = hp @ W_fin + b_fin (CLS=2) ----------------
__global__ __launch_bounds__(256) void final_kernel(
    const float* __restrict__ hp, const float* __restrict__ W,
    const float* __restrict__ bias, float* __restrict__ out)
{
    __shared__ float Ws[256];
    __shared__ float bs[2];
    if (threadIdx.x < 256) Ws[threadIdx.x] = W[threadIdx.x];
    if (threadIdx.x < 2)   bs[threadIdx.x] = bias[threadIdx.x];
    __syncthreads();
    size_t row = (size_t)blockIdx.x * blockDim.x + threadIdx.x;
    const float* hr = hp + row * 128;
    float a0 = bs[0], a1 = bs[1];
#pragma unroll
    for (int k = 0; k < 128; ++k) {
        float hv = hr[k];
        a0 += hv * Ws[2*k+0];
        a1 += hv * Ws[2*k+1];
    }
    out[row*2+0] = a0;
    out[row*2+1] = a1;
}

// ---------------- launch ----------------
extern "C" void kernel_launch(void* const* d_in, const int* in_sizes, int n_in,
                              void* d_out, int out_size) {
    const float* X     = (const float*)d_in[0];
    const float* A     = (const float*)d_in[1];
    const float* T     = (const float*)d_in[2];
    const float* theta = (const float*)d_in[3];
    const float* W_raw = (const float*)d_in[4];
    const float* b_raw = (const float*)d_in[5];
    const float* Wd0   = (const float*)d_in[6];
    const float* bd0   = (const float*)d_in[7];
    const float* Wd1   = (const float*)d_in[8];
    const float* bd1   = (const float*)d_in[9];
    const float* W_fin = (const float*)d_in[10];
    const float* b_fin = (const float*)d_in[11];
    const float* Wq0 = (const float*)d_in[12]; const float* bq0 = (const float*)d_in[13];
    const float* Wk0 = (const float*)d_in[14]; const float* bk0 = (const float*)d_in[15];
    const float* Wv0 = (const float*)d_in[16]; const float* bv0 = (const float*)d_in[17];
    const float* Wo0 = (const float*)d_in[18]; const float* bo0 = (const float*)d_in[19];
    const float* Wq1 = (const float*)d_in[20]; const float* bq1 = (const float*)d_in[21];
    const float* Wk1 = (const float*)d_in[22]; const float* bk1 = (const float*)d_in[23];
    const float* Wv1 = (const float*)d_in[24]; const float* bv1 = (const float*)d_in[25];
    const float* Wo1 = (const float*)d_in[26]; const float* bo1 = (const float*)d_in[27];

    float *Qm, *hp, *h, *z, *xc, *qb, *kb, *vb, *ctx;
    cudaGetSymbolAddress((void**)&Qm,  g_Q);
    cudaGetSymbolAddress((void**)&hp,  g_hp);
    cudaGetSymbolAddress((void**)&h,   g_h);
    cudaGetSymbolAddress((void**)&z,   g_z);
    cudaGetSymbolAddress((void**)&xc,  g_x);
    cudaGetSymbolAddress((void**)&qb,  g_qb);
    cudaGetSymbolAddress((void**)&kb,  g_kb);
    cudaGetSymbolAddress((void**)&vb,  g_vb);
    cudaGetSymbolAddress((void**)&ctx, g_ctx);

    const int attn_smem = (2 * 64 * 68 + 64 * 65) * (int)sizeof(float);  // 51456 B
    cudaFuncSetAttribute(attn_kernel, cudaFuncAttributeMaxDynamicSharedMemorySize, attn_smem);

    dim3 tgrid(2, M_ROWS / 64);          // N=128 outputs
    dim3 attn_grid(NNODE / 64, 2, NB);   // (q-tiles, heads, batch)

    // transition mixing
    theta_softmax_kernel<<<1, 32>>>(theta);
    qmix_kernel<<<2 * 1024 * 1024 / 256, 256>>>(T);

    // raw projection: hp = X @ W_raw + b_raw
    sgemm_kernel<<<tgrid, 256>>>(X, W_raw, b_raw, nullptr, hp, M_ROWS, 64, 128, 0);

    // layer 0 diffusion: h = relu((Q0⊙A)@X @ Wd0 + bd0)
    diff_gemm_kernel<<<dim3(1, 16, NB), 256>>>(Qm, A, X, z, 64);
    sgemm_kernel<<<tgrid, 256>>>(z, Wd0, bd0, nullptr, h, M_ROWS, 64, 128, 1);

    // layer 0 attention
    concat_kernel<<<M_ROWS * 256 / 256, 256>>>(h, hp, xc);
    sgemm_kernel<<<tgrid, 256>>>(xc, Wq0, bq0, nullptr, qb, M_ROWS, 256, 128, 0);
    sgemm_kernel<<<tgrid, 256>>>(xc, Wk0, bk0, nullptr, kb, M_ROWS, 256, 128, 0);
    sgemm_kernel<<<tgrid, 256>>>(xc, Wv0, bv0, nullptr, vb, M_ROWS, 256, 128, 0);
    attn_kernel<<<attn_grid, 64, attn_smem>>>(qb, kb, vb, ctx);
    sgemm_kernel<<<tgrid, 256>>>(ctx, Wo0, bo0, nullptr, hp, M_ROWS, 128, 128, 1);

    // layer 1 diffusion: h = relu((Q1⊙A)@h @ Wd1 + bd1)
    diff_gemm_kernel<<<dim3(2, 16, NB), 256>>>(Qm + 1024 * 1024, A, h, z, 128);
    sgemm_kernel<<<tgrid, 256>>>(z, Wd1, bd1, nullptr, h, M_ROWS, 128, 128, 1);

    // layer 1 attention with residual: hp = hp + relu(attn(...))
    concat_kernel<<<M_ROWS * 256 / 256, 256>>>(h, hp, xc);
    sgemm_kernel<<<tgrid, 256>>>(xc, Wq1, bq1, nullptr, qb, M_ROWS, 256, 128, 0);
    sgemm_kernel<<<tgrid, 256>>>(xc, Wk1, bk1, nullptr, kb, M_ROWS, 256, 128, 0);
    sgemm_kernel<<<tgrid, 256>>>(xc, Wv1, bv1, nullptr, vb, M_ROWS, 256, 128, 0);
    attn_kernel<<<attn_grid, 64, attn_smem>>>(qb, kb, vb, ctx);
    sgemm_kernel<<<tgrid, 256>>>(ctx, Wo1, bo1, hp, hp, M_ROWS, 128, 128, 1);

    // classifier
    final_kernel<<<M_ROWS / 256, 256>>>(hp, W_fin, b_fin, (float*)d_out);
}

// round 2
// speedup vs baseline: 1.3439x; 1.3439x over previous
#include <cuda_runtime.h>
#include <math.h>
#include <stdint.h>

#define M_ROWS 32768          // B*N
#define NB 32
#define NNODE 1024

// ---------------- scratch (device globals, allocation-free) ----------------
__device__ float g_thsm[6];
__device__ float g_Q[2u * 1024u * 1024u];          // mixed transition Q[2][N][N]
__device__ float g_hp [(size_t)M_ROWS * 128];      // h_prime
__device__ float g_h  [(size_t)M_ROWS * 128];      // diffusion output
__device__ float g_z  [(size_t)M_ROWS * 128];      // diffusion pre-linear
__device__ float g_qb [(size_t)M_ROWS * 128];
__device__ float g_kb [(size_t)M_ROWS * 128];
__device__ float g_vb [(size_t)M_ROWS * 128];
__device__ float g_ctx[(size_t)M_ROWS * 128];

// ---------------- helpers ----------------
__device__ __forceinline__ uint32_t f2tf32(float f) {
    uint32_t r;
    asm("cvt.rna.tf32.f32 %0, %1;" : "=r"(r) : "f"(f));
    return r;
}

__device__ __forceinline__ void mma_tf32(float* d, const uint32_t* a,
                                         const uint32_t* b, const float* c) {
    asm volatile(
        "mma.sync.aligned.m16n8k8.row.col.f32.tf32.tf32.f32 "
        "{%0,%1,%2,%3}, {%4,%5,%6,%7}, {%8,%9}, {%10,%11,%12,%13};\n"
        : "=f"(d[0]), "=f"(d[1]), "=f"(d[2]), "=f"(d[3])
        : "r"(a[0]), "r"(a[1]), "r"(a[2]), "r"(a[3]),
          "r"(b[0]), "r"(b[1]),
          "f"(c[0]), "f"(c[1]), "f"(c[2]), "f"(c[3]));
}

// ---------------- theta softmax (K=3, 2 layers) ----------------
__global__ void theta_softmax_kernel(const float* __restrict__ th) {
    int l = threadIdx.x;
    if (l < 2) {
        float a = th[l*3+0], b = th[l*3+1], c = th[l*3+2];
        float m = fmaxf(a, fmaxf(b, c));
        float ea = expf(a - m), eb = expf(b - m), ec = expf(c - m);
        float s = ea + eb + ec;
        g_thsm[l*3+0] = ea / s;
        g_thsm[l*3+1] = eb / s;
        g_thsm[l*3+2] = ec / s;
    }
}

// ---------------- Q[l] = sum_k thsm[l,k] * T[l,k] ----------------
__global__ void qmix_kernel(const float* __restrict__ T) {
    size_t i = (size_t)blockIdx.x * 256 + threadIdx.x;   // < 2*1048576
    size_t l  = i >> 20;
    size_t ij = i & 1048575u;
    const float* Tl = T + l * 3u * 1048576u;
    g_Q[i] = g_thsm[l*3+0] * Tl[ij]
           + g_thsm[l*3+1] * Tl[1048576u + ij]
           + g_thsm[l*3+2] * Tl[2u*1048576u + ij];
}

// ============ tf32 MMA dense GEMM: C = [base +] act([A1|A2]@W + bias) ============
// Output width fixed at 128. A = concat(A1[:, :K1], A2[:, :K-K1]) along cols.
// Block tile 128x128, 8 warps, each warp 32x64 via m16n8k8.
__global__ __launch_bounds__(256) void mma_gemm_kernel(
    const float* __restrict__ A1, const float* __restrict__ A2, int K1, int K,
    const float* __restrict__ W, const float* __restrict__ bias,
    const float* __restrict__ base, float* __restrict__ C, int relu)
{
    __shared__ uint32_t As[128][20];   // [m][k], stride 20 -> conflict-free frag loads
    __shared__ uint32_t Bs[16][136];   // [k][n], stride 136 -> conflict-free

    const int tid  = threadIdx.x;
    const int lane = tid & 31;
    const int w    = tid >> 5;
    const int wm   = w & 3;            // 0..3 -> rows wm*32
    const int wn   = w >> 2;           // 0..1 -> cols wn*64
    const int lr   = lane >> 2;        // 0..7
    const int lc   = lane & 3;         // 0..3
    const int row0 = blockIdx.x << 7;
    const int K2   = K - K1;

    float acc[2][8][4];
#pragma unroll
    for (int mt = 0; mt < 2; ++mt)
#pragma unroll
        for (int nt = 0; nt < 8; ++nt)
#pragma unroll
            for (int i = 0; i < 4; ++i) acc[mt][nt][i] = 0.f;

    for (int k0 = 0; k0 < K; k0 += 16) {
        __syncthreads();
        // stage A tile 128x16 (with concat source select)
#pragma unroll
        for (int i = 0; i < 2; ++i) {
            int L = tid + i * 256;
            int r = L >> 2, kq = (L & 3) << 2;
            int kg = k0 + kq;
            const float* src = (kg < K1) ? A1 : A2;
            int kk           = (kg < K1) ? kg : (kg - K1);
            int stride       = (kg < K1) ? K1 : K2;
            float4 v = *reinterpret_cast<const float4*>(
                src + (size_t)(row0 + r) * stride + kk);
            As[r][kq+0] = f2tf32(v.x);
            As[r][kq+1] = f2tf32(v.y);
            As[r][kq+2] = f2tf32(v.z);
            As[r][kq+3] = f2tf32(v.w);
        }
        // stage W tile 16x128
#pragma unroll
        for (int i = 0; i < 2; ++i) {
            int L = tid + i * 256;
            int kr = L >> 5, nc = (L & 31) << 2;
            float4 v = *reinterpret_cast<const float4*>(
                W + (size_t)(k0 + kr) * 128 + nc);
            Bs[kr][nc+0] = f2tf32(v.x);
            Bs[kr][nc+1] = f2tf32(v.y);
            Bs[kr][nc+2] = f2tf32(v.z);
            Bs[kr][nc+3] = f2tf32(v.w);
        }
        __syncthreads();

#pragma unroll
        for (int ksub = 0; ksub < 16; ksub += 8) {
            uint32_t a[2][4], b[8][2];
#pragma unroll
            for (int mt = 0; mt < 2; ++mt) {
                int rm = wm*32 + mt*16 + lr;
                a[mt][0] = As[rm    ][ksub + lc    ];
                a[mt][1] = As[rm + 8][ksub + lc    ];
                a[mt][2] = As[rm    ][ksub + lc + 4];
                a[mt][3] = As[rm + 8][ksub + lc + 4];
            }
#pragma unroll
            for (int nt = 0; nt < 8; ++nt) {
                int nb = wn*64 + nt*8 + lr;
                b[nt][0] = Bs[ksub + lc    ][nb];
                b[nt][1] = Bs[ksub + lc + 4][nb];
            }
#pragma unroll
            for (int mt = 0; mt < 2; ++mt)
#pragma unroll
                for (int nt = 0; nt < 8; ++nt)
                    mma_tf32(acc[mt][nt], a[mt], b[nt], acc[mt][nt]);
        }
    }

    // epilogue
#pragma unroll
    for (int mt = 0; mt < 2; ++mt) {
#pragma unroll
        for (int nt = 0; nt < 8; ++nt) {
            int col = wn*64 + nt*8 + 2*lc;
            float b0 = bias[col], b1 = bias[col+1];
#pragma unroll
            for (int half = 0; half < 2; ++half) {
                int row = row0 + wm*32 + mt*16 + lr + half*8;
                float v0 = acc[mt][nt][half*2+0] + b0;
                float v1 = acc[mt][nt][half*2+1] + b1;
                if (relu) { v0 = fmaxf(v0, 0.f); v1 = fmaxf(v1, 0.f); }
                if (base) {
                    const float2 bv = *reinterpret_cast<const float2*>(
                        base + (size_t)row * 128 + col);
                    v0 += bv.x; v1 += bv.y;
                }
                float2 o; o.x = v0; o.y = v1;
                *reinterpret_cast<float2*>(C + (size_t)row * 128 + col) = o;
            }
        }
    }
}

// ====== tf32 MMA masked diffusion GEMM: Z[b] = (Qm ⊙ Adj[b]) @ Hin[b] ======
// BN = feature width (64 or 128). Block tile 128 x BN, contraction over 1024 nodes.
template<int BN>
__global__ __launch_bounds__(256) void diff_mma_kernel(
    const float* __restrict__ Qm, const float* __restrict__ Adj,
    const float* __restrict__ Hin, float* __restrict__ Z)
{
    constexpr int WN = BN / 2;     // warp col extent
    constexpr int NT = WN / 8;     // n-tiles per warp (4 or 8)

    __shared__ uint32_t As[128][20];
    __shared__ uint32_t Bs[16][BN + 8];

    const int tid  = threadIdx.x;
    const int lane = tid & 31;
    const int w    = tid >> 5;
    const int wm   = w & 3;
    const int wn   = w >> 2;
    const int lr   = lane >> 2;
    const int lc   = lane & 3;
    const int b    = blockIdx.z;
    const int i0   = blockIdx.x << 7;
    const size_t adjb = (size_t)b * NNODE * NNODE;
    const size_t hb   = (size_t)b * NNODE * BN;

    float acc[2][NT][4];
#pragma unroll
    for (int mt = 0; mt < 2; ++mt)
#pragma unroll
        for (int nt = 0; nt < NT; ++nt)
#pragma unroll
            for (int i = 0; i < 4; ++i) acc[mt][nt][i] = 0.f;

    for (int j0 = 0; j0 < NNODE; j0 += 16) {
        __syncthreads();
        // stage P = Q ⊙ Adj tile 128x16
#pragma unroll
        for (int i = 0; i < 2; ++i) {
            int L = tid + i * 256;
            int r = L >> 2, kq = (L & 3) << 2;
            size_t off = (size_t)(i0 + r) * NNODE + j0 + kq;
            float4 qv = *reinterpret_cast<const float4*>(Qm + off);
            float4 av = *reinterpret_cast<const float4*>(Adj + adjb + off);
            As[r][kq+0] = f2tf32(qv.x * av.x);
            As[r][kq+1] = f2tf32(qv.y * av.y);
            As[r][kq+2] = f2tf32(qv.z * av.z);
            As[r][kq+3] = f2tf32(qv.w * av.w);
        }
        // stage H tile 16xBN
#pragma unroll
        for (int i = 0; i < BN/64; ++i) {
            int L = tid + i * 256;
            int kr = L / (BN/4), nc = (L % (BN/4)) << 2;
            float4 v = *reinterpret_cast<const float4*>(
                Hin + hb + (size_t)(j0 + kr) * BN + nc);
            Bs[kr][nc+0] = f2tf32(v.x);
            Bs[kr][nc+1] = f2tf32(v.y);
            Bs[kr][nc+2] = f2tf32(v.z);
            Bs[kr][nc+3] = f2tf32(v.w);
        }
        __syncthreads();

#pragma unroll
        for (int ksub = 0; ksub < 16; ksub += 8) {
            uint32_t a[2][4], bf[NT][2];
#pragma unroll
            for (int mt = 0; mt < 2; ++mt) {
                int rm = wm*32 + mt*16 + lr;
                a[mt][0] = As[rm    ][ksub + lc    ];
                a[mt][1] = As[rm + 8][ksub + lc    ];
                a[mt][2] = As[rm    ][ksub + lc + 4];
                a[mt][3] = As[rm + 8][ksub + lc + 4];
            }
#pragma unroll
            for (int nt = 0; nt < NT; ++nt) {
                int nb = wn*WN + nt*8 + lr;
                bf[nt][0] = Bs[ksub + lc    ][nb];
                bf[nt][1] = Bs[ksub + lc + 4][nb];
            }
#pragma unroll
            for (int mt = 0; mt < 2; ++mt)
#pragma unroll
                for (int nt = 0; nt < NT; ++nt)
                    mma_tf32(acc[mt][nt], a[mt], bf[nt], acc[mt][nt]);
        }
    }

#pragma unroll
    for (int mt = 0; mt < 2; ++mt) {
#pragma unroll
        for (int nt = 0; nt < NT; ++nt) {
            int col = wn*WN + nt*8 + 2*lc;
#pragma unroll
            for (int half = 0; half < 2; ++half) {
                int row = i0 + wm*32 + mt*16 + lr + half*8;
                float2 o;
                o.x = acc[mt][nt][half*2+0];
                o.y = acc[mt][nt][half*2+1];
                *reinterpret_cast<float2*>(Z + hb + (size_t)row * BN + col) = o;
            }
        }
    }
}

// ---------------- flash attention: H=2 heads, d=64, N=1024 ----------------
// grid (N/64, H, B); 64 threads = 1 thread per query row
__global__ __launch_bounds__(64) void attn_kernel(
    const float* __restrict__ Q, const float* __restrict__ K,
    const float* __restrict__ V, float* __restrict__ O)
{
    extern __shared__ __align__(16) float sm[];
    float* Ks = sm;                  // [64][68]
    float* Vs = sm + 64 * 68;        // [64][68]
    float* Ss = sm + 2 * 64 * 68;    // [64][65]
    const int tid = threadIdx.x;
    const int b = blockIdx.z, h = blockIdx.y;
    const int q0 = blockIdx.x * 64;
    const size_t rb = (size_t)b * NNODE;
    const int hoff = h * 64;

    for (int it = 0; it < 64; ++it)
        Ks[it * 68 + tid] = Q[(rb + q0 + it) * 128 + hoff + tid];
    __syncthreads();
    float qreg[64];
#pragma unroll
    for (int d = 0; d < 64; ++d) qreg[d] = Ks[tid * 68 + d] * 0.125f;

    float m = -1e30f, l = 0.f;
    float acc[64];
#pragma unroll
    for (int d = 0; d < 64; ++d) acc[d] = 0.f;

    for (int j0 = 0; j0 < NNODE; j0 += 64) {
        __syncthreads();
        for (int it = 0; it < 64; ++it) {
            Ks[it * 68 + tid] = K[(rb + j0 + it) * 128 + hoff + tid];
            Vs[it * 68 + tid] = V[(rb + j0 + it) * 128 + hoff + tid];
        }
        __syncthreads();

        float tmax = -1e30f;
        for (int j = 0; j < 64; ++j) {
            const float4* kr = reinterpret_cast<const float4*>(Ks + j * 68);
            float s0 = 0.f, s1 = 0.f, s2 = 0.f, s3 = 0.f;
#pragma unroll
            for (int d4 = 0; d4 < 16; ++d4) {
                float4 kv = kr[d4];
                s0 += qreg[d4*4+0] * kv.x;
                s1 += qreg[d4*4+1] * kv.y;
                s2 += qreg[d4*4+2] * kv.z;
                s3 += qreg[d4*4+3] * kv.w;
            }
            float s = (s0 + s1) + (s2 + s3);
            Ss[tid * 65 + j] = s;
            tmax = fmaxf(tmax, s);
        }
        float mt = fmaxf(m, tmax);
        float corr = __expf(m - mt);
        l *= corr;
#pragma unroll
        for (int d = 0; d < 64; ++d) acc[d] *= corr;
        for (int j = 0; j < 64; ++j) {
            float p = __expf(Ss[tid * 65 + j] - mt);
            l += p;
            const float4* vr = reinterpret_cast<const float4*>(Vs + j * 68);
#pragma unroll
            for (int d4 = 0; d4 < 16; ++d4) {
                float4 vv = vr[d4];
                acc[d4*4+0] += p * vv.x;
                acc[d4*4+1] += p * vv.y;
                acc[d4*4+2] += p * vv.z;
                acc[d4*4+3] += p * vv.w;
            }
        }
        m = mt;
    }
    float inv = 1.f / l;
#pragma unroll
    for (int d = 0; d < 64; ++d)
        O[(rb + q0 + tid) * 128 + hoff + d] = acc[d] * inv;
}

// ---------------- final classifier: out = hp @ W_fin + b_fin (CLS=2) ----------------
__global__ __launch_bounds__(256) void final_kernel(
    const float* __restrict__ hp, const float* __restrict__ W,
    const float* __restrict__ bias, float* __restrict__ out)
{
    __shared__ float Ws[256];
    __shared__ float bs[2];
    if (threadIdx.x < 256) Ws[threadIdx.x] = W[threadIdx.x];
    if (threadIdx.x < 2)   bs[threadIdx.x] = bias[threadIdx.x];
    __syncthreads();
    size_t row = (size_t)blockIdx.x * blockDim.x + threadIdx.x;
    const float* hr = hp + row * 128;
    float a0 = bs[0], a1 = bs[1];
#pragma unroll
    for (int k = 0; k < 128; ++k) {
        float hv = hr[k];
        a0 += hv * Ws[2*k+0];
        a1 += hv * Ws[2*k+1];
    }
    out[row*2+0] = a0;
    out[row*2+1] = a1;
}

// ---------------- launch ----------------
extern "C" void kernel_launch(void* const* d_in, const int* in_sizes, int n_in,
                              void* d_out, int out_size) {
    const float* X     = (const float*)d_in[0];
    const float* A     = (const float*)d_in[1];
    const float* T     = (const float*)d_in[2];
    const float* theta = (const float*)d_in[3];
    const float* W_raw = (const float*)d_in[4];
    const float* b_raw = (const float*)d_in[5];
    const float* Wd0   = (const float*)d_in[6];
    const float* bd0   = (const float*)d_in[7];
    const float* Wd1   = (const float*)d_in[8];
    const float* bd1   = (const float*)d_in[9];
    const float* W_fin = (const float*)d_in[10];
    const float* b_fin = (const float*)d_in[11];
    const float* Wq0 = (const float*)d_in[12]; const float* bq0 = (const float*)d_in[13];
    const float* Wk0 = (const float*)d_in[14]; const float* bk0 = (const float*)d_in[15];
    const float* Wv0 = (const float*)d_in[16]; const float* bv0 = (const float*)d_in[17];
    const float* Wo0 = (const float*)d_in[18]; const float* bo0 = (const float*)d_in[19];
    const float* Wq1 = (const float*)d_in[20]; const float* bq1 = (const float*)d_in[21];
    const float* Wk1 = (const float*)d_in[22]; const float* bk1 = (const float*)d_in[23];
    const float* Wv1 = (const float*)d_in[24]; const float* bv1 = (const float*)d_in[25];
    const float* Wo1 = (const float*)d_in[26]; const float* bo1 = (const float*)d_in[27];

    float *Qm, *hp, *h, *z, *qb, *kb, *vb, *ctx;
    cudaGetSymbolAddress((void**)&Qm,  g_Q);
    cudaGetSymbolAddress((void**)&hp,  g_hp);
    cudaGetSymbolAddress((void**)&h,   g_h);
    cudaGetSymbolAddress((void**)&z,   g_z);
    cudaGetSymbolAddress((void**)&qb,  g_qb);
    cudaGetSymbolAddress((void**)&kb,  g_kb);
    cudaGetSymbolAddress((void**)&vb,  g_vb);
    cudaGetSymbolAddress((void**)&ctx, g_ctx);

    const int attn_smem = (2 * 64 * 68 + 64 * 65) * (int)sizeof(float);  // 51456 B
    cudaFuncSetAttribute(attn_kernel, cudaFuncAttributeMaxDynamicSharedMemorySize, attn_smem);

    const int ggrid = M_ROWS / 128;              // 256 blocks
    dim3 dgrid(NNODE / 128, 1, NB);              // diffusion: per-batch rows
    dim3 attn_grid(NNODE / 64, 2, NB);

    // transition mixing
    theta_softmax_kernel<<<1, 32>>>(theta);
    qmix_kernel<<<2 * 1024 * 1024 / 256, 256>>>(T);

    // raw projection: hp = X @ W_raw + b_raw
    mma_gemm_kernel<<<ggrid, 256>>>(X, X, 64, 64, W_raw, b_raw, nullptr, hp, 0);

    // layer 0 diffusion: h = relu(((Q0⊙A)@X) @ Wd0 + bd0)
    diff_mma_kernel<64><<<dgrid, 256>>>(Qm, A, X, z);
    mma_gemm_kernel<<<ggrid, 256>>>(z, z, 64, 64, Wd0, bd0, nullptr, h, 1);

    // layer 0 attention (concat fused into GEMM A-source)
    mma_gemm_kernel<<<ggrid, 256>>>(h, hp, 128, 256, Wq0, bq0, nullptr, qb, 0);
    mma_gemm_kernel<<<ggrid, 256>>>(h, hp, 128, 256, Wk0, bk0, nullptr, kb, 0);
    mma_gemm_kernel<<<ggrid, 256>>>(h, hp, 128, 256, Wv0, bv0, nullptr, vb, 0);
    attn_kernel<<<attn_grid, 64, attn_smem>>>(qb, kb, vb, ctx);
    mma_gemm_kernel<<<ggrid, 256>>>(ctx, ctx, 128, 128, Wo0, bo0, nullptr, hp, 1);

    // layer 1 diffusion: h = relu(((Q1⊙A)@h) @ Wd1 + bd1)
    diff_mma_kernel<128><<<dgrid, 256>>>(Qm + 1024 * 1024, A, h, z);
    mma_gemm_kernel<<<ggrid, 256>>>(z, z, 128, 128, Wd1, bd1, nullptr, h, 1);

    // layer 1 attention with residual: hp = hp + relu(attn(...))
    mma_gemm_kernel<<<ggrid, 256>>>(h, hp, 128, 256, Wq1, bq1, nullptr, qb, 0);
    mma_gemm_kernel<<<ggrid, 256>>>(h, hp, 128, 256, Wk1, bk1, nullptr, kb, 0);
    mma_gemm_kernel<<<ggrid, 256>>>(h, hp, 128, 256, Wv1, bv1, nullptr, vb, 0);
    attn_kernel<<<attn_grid, 64, attn_smem>>>(qb, kb, vb, ctx);
    mma_gemm_kernel<<<ggrid, 256>>>(ctx, ctx, 128, 128, Wo1, bo1, hp, hp, 1);

    // classifier
    final_kernel<<<M_ROWS / 256, 256>>>(hp, W_fin, b_fin, (float*)d_out);
}

// round 3
// speedup vs baseline: 3.0106x; 2.2402x over previous
#include <cuda_runtime.h>
#include <math.h>
#include <stdint.h>

#define M_ROWS 32768          // B*N
#define NB 32
#define NNODE 1024

// ---------------- scratch (device globals, allocation-free) ----------------
__device__ float g_thsm[6];
__device__ float g_Q[2u * 1024u * 1024u];          // mixed transition Q[2][N][N]
__device__ float g_hp [(size_t)M_ROWS * 128];      // h_prime
__device__ float g_h  [(size_t)M_ROWS * 128];      // diffusion output
__device__ float g_z  [(size_t)M_ROWS * 128];      // diffusion pre-linear
__device__ float g_qb [(size_t)M_ROWS * 128];
__device__ float g_kb [(size_t)M_ROWS * 128];
__device__ float g_vb [(size_t)M_ROWS * 128];
__device__ float g_ctx[(size_t)M_ROWS * 128];

// ---------------- helpers ----------------
__device__ __forceinline__ uint32_t f2tf32(float f) {
    uint32_t r;
    asm("cvt.rna.tf32.f32 %0, %1;" : "=r"(r) : "f"(f));
    return r;
}

__device__ __forceinline__ void mma_tf32(float* d, const uint32_t* a,
                                         const uint32_t* b, const float* c) {
    asm volatile(
        "mma.sync.aligned.m16n8k8.row.col.f32.tf32.tf32.f32 "
        "{%0,%1,%2,%3}, {%4,%5,%6,%7}, {%8,%9}, {%10,%11,%12,%13};\n"
        : "=f"(d[0]), "=f"(d[1]), "=f"(d[2]), "=f"(d[3])
        : "r"(a[0]), "r"(a[1]), "r"(a[2]), "r"(a[3]),
          "r"(b[0]), "r"(b[1]),
          "f"(c[0]), "f"(c[1]), "f"(c[2]), "f"(c[3]));
}

// ---------------- theta softmax (K=3, 2 layers) ----------------
__global__ void theta_softmax_kernel(const float* __restrict__ th) {
    int l = threadIdx.x;
    if (l < 2) {
        float a = th[l*3+0], b = th[l*3+1], c = th[l*3+2];
        float m = fmaxf(a, fmaxf(b, c));
        float ea = expf(a - m), eb = expf(b - m), ec = expf(c - m);
        float s = ea + eb + ec;
        g_thsm[l*3+0] = ea / s;
        g_thsm[l*3+1] = eb / s;
        g_thsm[l*3+2] = ec / s;
    }
}

// ---------------- Q[l] = sum_k thsm[l,k] * T[l,k] ----------------
__global__ void qmix_kernel(const float* __restrict__ T) {
    size_t i = (size_t)blockIdx.x * 256 + threadIdx.x;   // < 2*1048576
    size_t l  = i >> 20;
    size_t ij = i & 1048575u;
    const float* Tl = T + l * 3u * 1048576u;
    g_Q[i] = g_thsm[l*3+0] * Tl[ij]
           + g_thsm[l*3+1] * Tl[1048576u + ij]
           + g_thsm[l*3+2] * Tl[2u*1048576u + ij];
}

// ============ tf32 MMA dense GEMM: C = [base +] act([A1|A2]@W + bias) ============
// Output width fixed at 128. Double-buffered smem + register prefetch.
__global__ __launch_bounds__(256) void mma_gemm_kernel(
    const float* __restrict__ A1, const float* __restrict__ A2, int K1, int K,
    const float* __restrict__ W, const float* __restrict__ bias,
    const float* __restrict__ base, float* __restrict__ C, int relu)
{
    __shared__ uint32_t As[2][128][20];
    __shared__ uint32_t Bs[2][16][136];

    const int tid  = threadIdx.x;
    const int lane = tid & 31;
    const int w    = tid >> 5;
    const int wm   = w & 3;
    const int wn   = w >> 2;
    const int lr   = lane >> 2;
    const int lc   = lane & 3;
    const int row0 = blockIdx.x << 7;
    const int K2   = K - K1;

    float4 pa[2], pw[2];

#define GEMM_LDG(k0)                                                          \
    {                                                                          \
        _Pragma("unroll")                                                      \
        for (int i = 0; i < 2; ++i) {                                          \
            int L = tid + i * 256;                                             \
            int r = L >> 2, kq = (L & 3) << 2;                                 \
            int kg = (k0) + kq;                                                \
            const float* src = (kg < K1) ? A1 : A2;                            \
            int kk     = (kg < K1) ? kg : (kg - K1);                           \
            int stride = (kg < K1) ? K1 : K2;                                  \
            pa[i] = *reinterpret_cast<const float4*>(                          \
                src + (size_t)(row0 + r) * stride + kk);                       \
        }                                                                      \
        _Pragma("unroll")                                                      \
        for (int i = 0; i < 2; ++i) {                                          \
            int L = tid + i * 256;                                             \
            int kr = L >> 5, nc = (L & 31) << 2;                               \
            pw[i] = *reinterpret_cast<const float4*>(                          \
                W + (size_t)((k0) + kr) * 128 + nc);                           \
        }                                                                      \
    }

#define GEMM_STS(bufi)                                                        \
    {                                                                          \
        _Pragma("unroll")                                                      \
        for (int i = 0; i < 2; ++i) {                                          \
            int L = tid + i * 256;                                             \
            int r = L >> 2, kq = (L & 3) << 2;                                 \
            As[bufi][r][kq+0] = f2tf32(pa[i].x);                               \
            As[bufi][r][kq+1] = f2tf32(pa[i].y);                               \
            As[bufi][r][kq+2] = f2tf32(pa[i].z);                               \
            As[bufi][r][kq+3] = f2tf32(pa[i].w);                               \
        }                                                                      \
        _Pragma("unroll")                                                      \
        for (int i = 0; i < 2; ++i) {                                          \
            int L = tid + i * 256;                                             \
            int kr = L >> 5, nc = (L & 31) << 2;                               \
            Bs[bufi][kr][nc+0] = f2tf32(pw[i].x);                              \
            Bs[bufi][kr][nc+1] = f2tf32(pw[i].y);                              \
            Bs[bufi][kr][nc+2] = f2tf32(pw[i].z);                              \
            Bs[bufi][kr][nc+3] = f2tf32(pw[i].w);                              \
        }                                                                      \
    }

    float acc[2][8][4];
#pragma unroll
    for (int mt = 0; mt < 2; ++mt)
#pragma unroll
        for (int nt = 0; nt < 8; ++nt)
#pragma unroll
            for (int i = 0; i < 4; ++i) acc[mt][nt][i] = 0.f;

    GEMM_LDG(0);
    GEMM_STS(0);
    __syncthreads();

    int buf = 0;
    for (int k0 = 0; k0 < K; k0 += 16) {
        const bool has_next = (k0 + 16 < K);
        if (has_next) GEMM_LDG(k0 + 16);

#pragma unroll
        for (int ksub = 0; ksub < 16; ksub += 8) {
            uint32_t a[2][4], b[8][2];
#pragma unroll
            for (int mt = 0; mt < 2; ++mt) {
                int rm = wm*32 + mt*16 + lr;
                a[mt][0] = As[buf][rm    ][ksub + lc    ];
                a[mt][1] = As[buf][rm + 8][ksub + lc    ];
                a[mt][2] = As[buf][rm    ][ksub + lc + 4];
                a[mt][3] = As[buf][rm + 8][ksub + lc + 4];
            }
#pragma unroll
            for (int nt = 0; nt < 8; ++nt) {
                int nb = wn*64 + nt*8 + lr;
                b[nt][0] = Bs[buf][ksub + lc    ][nb];
                b[nt][1] = Bs[buf][ksub + lc + 4][nb];
            }
#pragma unroll
            for (int mt = 0; mt < 2; ++mt)
#pragma unroll
                for (int nt = 0; nt < 8; ++nt)
                    mma_tf32(acc[mt][nt], a[mt], b[nt], acc[mt][nt]);
        }

        if (has_next) GEMM_STS(buf ^ 1);
        __syncthreads();
        buf ^= 1;
    }

    // epilogue
#pragma unroll
    for (int mt = 0; mt < 2; ++mt) {
#pragma unroll
        for (int nt = 0; nt < 8; ++nt) {
            int col = wn*64 + nt*8 + 2*lc;
            float b0 = bias[col], b1 = bias[col+1];
#pragma unroll
            for (int half = 0; half < 2; ++half) {
                int row = row0 + wm*32 + mt*16 + lr + half*8;
                float v0 = acc[mt][nt][half*2+0] + b0;
                float v1 = acc[mt][nt][half*2+1] + b1;
                if (relu) { v0 = fmaxf(v0, 0.f); v1 = fmaxf(v1, 0.f); }
                if (base) {
                    const float2 bv = *reinterpret_cast<const float2*>(
                        base + (size_t)row * 128 + col);
                    v0 += bv.x; v1 += bv.y;
                }
                float2 o; o.x = v0; o.y = v1;
                *reinterpret_cast<float2*>(C + (size_t)row * 128 + col) = o;
            }
        }
    }
#undef GEMM_LDG
#undef GEMM_STS
}

// ====== tf32 MMA masked diffusion GEMM: Z[b] = (Qm ⊙ Adj[b]) @ Hin[b] ======
// Double-buffered smem + register prefetch. BN = feature width (64 or 128).
template<int BN>
__global__ __launch_bounds__(256) void diff_mma_kernel(
    const float* __restrict__ Qm, const float* __restrict__ Adj,
    const float* __restrict__ Hin, float* __restrict__ Z)
{
    constexpr int WN = BN / 2;
    constexpr int NT = WN / 8;
    constexpr int NH = BN / 64;    // H-tile float4 loads per thread

    __shared__ uint32_t As[2][128][20];
    __shared__ uint32_t Bs[2][16][BN + 8];

    const int tid  = threadIdx.x;
    const int lane = tid & 31;
    const int w    = tid >> 5;
    const int wm   = w & 3;
    const int wn   = w >> 2;
    const int lr   = lane >> 2;
    const int lc   = lane & 3;
    const int b    = blockIdx.z;
    const int i0   = blockIdx.x << 7;
    const size_t adjb = (size_t)b * NNODE * NNODE;
    const size_t hb   = (size_t)b * NNODE * BN;

    float4 qv[2], av[2], hv[NH];

#define DIFF_LDG(j0)                                                           \
    {                                                                          \
        _Pragma("unroll")                                                      \
        for (int i = 0; i < 2; ++i) {                                          \
            int L = tid + i * 256;                                             \
            int r = L >> 2, kq = (L & 3) << 2;                                 \
            size_t off = (size_t)(i0 + r) * NNODE + (j0) + kq;                 \
            qv[i] = *reinterpret_cast<const float4*>(Qm + off);                \
            av[i] = *reinterpret_cast<const float4*>(Adj + adjb + off);        \
        }                                                                      \
        _Pragma("unroll")                                                      \
        for (int i = 0; i < NH; ++i) {                                         \
            int L = tid + i * 256;                                             \
            int kr = L / (BN/4), nc = (L % (BN/4)) << 2;                       \
            hv[i] = *reinterpret_cast<const float4*>(                          \
                Hin + hb + (size_t)((j0) + kr) * BN + nc);                     \
        }                                                                      \
    }

#define DIFF_STS(bufi)                                                        \
    {                                                                          \
        _Pragma("unroll")                                                      \
        for (int i = 0; i < 2; ++i) {                                          \
            int L = tid + i * 256;                                             \
            int r = L >> 2, kq = (L & 3) << 2;                                 \
            As[bufi][r][kq+0] = f2tf32(qv[i].x * av[i].x);                     \
            As[bufi][r][kq+1] = f2tf32(qv[i].y * av[i].y);                     \
            As[bufi][r][kq+2] = f2tf32(qv[i].z * av[i].z);                     \
            As[bufi][r][kq+3] = f2tf32(qv[i].w * av[i].w);                     \
        }                                                                      \
        _Pragma("unroll")                                                      \
        for (int i = 0; i < NH; ++i) {                                         \
            int L = tid + i * 256;                                             \
            int kr = L / (BN/4), nc = (L % (BN/4)) << 2;                       \
            Bs[bufi][kr][nc+0] = f2tf32(hv[i].x);                              \
            Bs[bufi][kr][nc+1] = f2tf32(hv[i].y);                              \
            Bs[bufi][kr][nc+2] = f2tf32(hv[i].z);                              \
            Bs[bufi][kr][nc+3] = f2tf32(hv[i].w);                              \
        }                                                                      \
    }

    float acc[2][NT][4];
#pragma unroll
    for (int mt = 0; mt < 2; ++mt)
#pragma unroll
        for (int nt = 0; nt < NT; ++nt)
#pragma unroll
            for (int i = 0; i < 4; ++i) acc[mt][nt][i] = 0.f;

    DIFF_LDG(0);
    DIFF_STS(0);
    __syncthreads();

    int buf = 0;
    for (int j0 = 0; j0 < NNODE; j0 += 16) {
        const bool has_next = (j0 + 16 < NNODE);
        if (has_next) DIFF_LDG(j0 + 16);

#pragma unroll
        for (int ksub = 0; ksub < 16; ksub += 8) {
            uint32_t a[2][4], bf[NT][2];
#pragma unroll
            for (int mt = 0; mt < 2; ++mt) {
                int rm = wm*32 + mt*16 + lr;
                a[mt][0] = As[buf][rm    ][ksub + lc    ];
                a[mt][1] = As[buf][rm + 8][ksub + lc    ];
                a[mt][2] = As[buf][rm    ][ksub + lc + 4];
                a[mt][3] = As[buf][rm + 8][ksub + lc + 4];
            }
#pragma unroll
            for (int nt = 0; nt < NT; ++nt) {
                int nb = wn*WN + nt*8 + lr;
                bf[nt][0] = Bs[buf][ksub + lc    ][nb];
                bf[nt][1] = Bs[buf][ksub + lc + 4][nb];
            }
#pragma unroll
            for (int mt = 0; mt < 2; ++mt)
#pragma unroll
                for (int nt = 0; nt < NT; ++nt)
                    mma_tf32(acc[mt][nt], a[mt], bf[nt], acc[mt][nt]);
        }

        if (has_next) DIFF_STS(buf ^ 1);
        __syncthreads();
        buf ^= 1;
    }

#pragma unroll
    for (int mt = 0; mt < 2; ++mt) {
#pragma unroll
        for (int nt = 0; nt < NT; ++nt) {
            int col = wn*WN + nt*8 + 2*lc;
#pragma unroll
            for (int half = 0; half < 2; ++half) {
                int row = i0 + wm*32 + mt*16 + lr + half*8;
                float2 o;
                o.x = acc[mt][nt][half*2+0];
                o.y = acc[mt][nt][half*2+1];
                *reinterpret_cast<float2*>(Z + hb + (size_t)row * BN + col) = o;
            }
        }
    }
#undef DIFF_LDG
#undef DIFF_STS
}

// ========== tf32 MMA flash attention: H=2 heads, d=64, N=1024 ==========
// Block: 256 threads (8 warps), 128 queries; warp w owns rows w*16..w*16+15.
// grid (N/128, H, B). Q frags register-resident; P routed via Q smem strip.
__global__ __launch_bounds__(256) void attn_mma_kernel(
    const float* __restrict__ Qg, const float* __restrict__ Kg,
    const float* __restrict__ Vg, float* __restrict__ Og)
{
    extern __shared__ __align__(16) uint32_t smx[];
    uint32_t (*Qs)[68] = reinterpret_cast<uint32_t(*)[68]>(smx);              // 128x68, reused as P
    uint32_t (*Ks)[68] = reinterpret_cast<uint32_t(*)[68]>(smx + 128*68);     // 64x68
    uint32_t (*Vs)[68] = reinterpret_cast<uint32_t(*)[68]>(smx + 192*68);     // 64x68

    const int tid  = threadIdx.x;
    const int lane = tid & 31;
    const int w    = tid >> 5;
    const int lr   = lane >> 2;
    const int lc   = lane & 3;
    const int b    = blockIdx.z, h = blockIdx.y;
    const int q0   = blockIdx.x << 7;
    const size_t rb = (size_t)b * NNODE;
    const int hoff = h * 64;

    // stage Q tile (scaled by 1/sqrt(64), tf32)
#pragma unroll
    for (int i = 0; i < 8; ++i) {
        int L = tid + i * 256;
        int r = L >> 4, c = (L & 15) << 2;
        float4 v = *reinterpret_cast<const float4*>(
            Qg + (rb + q0 + r) * 128 + hoff + c);
        uint4 u;
        u.x = f2tf32(v.x * 0.125f); u.y = f2tf32(v.y * 0.125f);
        u.z = f2tf32(v.z * 0.125f); u.w = f2tf32(v.w * 0.125f);
        *reinterpret_cast<uint4*>(&Qs[r][c]) = u;
    }
    __syncthreads();

    // Q fragments into registers (whole kernel)
    uint32_t qa[8][4];
#pragma unroll
    for (int ks = 0; ks < 8; ++ks) {
        qa[ks][0] = Qs[w*16 + lr    ][ks*8 + lc    ];
        qa[ks][1] = Qs[w*16 + lr + 8][ks*8 + lc    ];
        qa[ks][2] = Qs[w*16 + lr    ][ks*8 + lc + 4];
        qa[ks][3] = Qs[w*16 + lr + 8][ks*8 + lc + 4];
    }

    float m0 = -1e30f, m1 = -1e30f, l0 = 0.f, l1 = 0.f;
    float oacc[8][4];
#pragma unroll
    for (int nt = 0; nt < 8; ++nt)
#pragma unroll
        for (int i = 0; i < 4; ++i) oacc[nt][i] = 0.f;

    for (int j0 = 0; j0 < NNODE; j0 += 64) {
        // stage K,V chunk 64x64 each
#pragma unroll
        for (int i = 0; i < 4; ++i) {
            int L = tid + i * 256;
            int r = L >> 4, c = (L & 15) << 2;
            float4 kv = *reinterpret_cast<const float4*>(
                Kg + (rb + j0 + r) * 128 + hoff + c);
            float4 vv = *reinterpret_cast<const float4*>(
                Vg + (rb + j0 + r) * 128 + hoff + c);
            uint4 uk, uv;
            uk.x = f2tf32(kv.x); uk.y = f2tf32(kv.y);
            uk.z = f2tf32(kv.z); uk.w = f2tf32(kv.w);
            uv.x = f2tf32(vv.x); uv.y = f2tf32(vv.y);
            uv.z = f2tf32(vv.z); uv.w = f2tf32(vv.w);
            *reinterpret_cast<uint4*>(&Ks[r][c]) = uk;
            *reinterpret_cast<uint4*>(&Vs[r][c]) = uv;
        }
        __syncthreads();   // also orders prev-iter P reads before this-iter P writes

        // S = Q @ K^T  (per warp: 16 x 64)
        float sacc[8][4];
#pragma unroll
        for (int nt = 0; nt < 8; ++nt)
#pragma unroll
            for (int i = 0; i < 4; ++i) sacc[nt][i] = 0.f;
#pragma unroll
        for (int ks = 0; ks < 8; ++ks) {
#pragma unroll
            for (int nt = 0; nt < 8; ++nt) {
                uint32_t bf[2];
                bf[0] = Ks[nt*8 + lr][ks*8 + lc    ];
                bf[1] = Ks[nt*8 + lr][ks*8 + lc + 4];
                mma_tf32(sacc[nt], qa[ks], bf, sacc[nt]);
            }
        }

        // online softmax (rows: lr -> half0, lr+8 -> half1)
        float rmax0 = -1e30f, rmax1 = -1e30f;
#pragma unroll
        for (int nt = 0; nt < 8; ++nt) {
            rmax0 = fmaxf(rmax0, fmaxf(sacc[nt][0], sacc[nt][1]));
            rmax1 = fmaxf(rmax1, fmaxf(sacc[nt][2], sacc[nt][3]));
        }
        rmax0 = fmaxf(rmax0, __shfl_xor_sync(0xffffffffu, rmax0, 1));
        rmax0 = fmaxf(rmax0, __shfl_xor_sync(0xffffffffu, rmax0, 2));
        rmax1 = fmaxf(rmax1, __shfl_xor_sync(0xffffffffu, rmax1, 1));
        rmax1 = fmaxf(rmax1, __shfl_xor_sync(0xffffffffu, rmax1, 2));

        float mn0 = fmaxf(m0, rmax0), mn1 = fmaxf(m1, rmax1);
        float cr0 = __expf(m0 - mn0), cr1 = __expf(m1 - mn1);
        m0 = mn0; m1 = mn1;

        float rs0 = 0.f, rs1 = 0.f;
#pragma unroll
        for (int nt = 0; nt < 8; ++nt) {
            float p00 = __expf(sacc[nt][0] - mn0);
            float p01 = __expf(sacc[nt][1] - mn0);
            float p10 = __expf(sacc[nt][2] - mn1);
            float p11 = __expf(sacc[nt][3] - mn1);
            rs0 += p00 + p01;
            rs1 += p10 + p11;
            uint2 u0; u0.x = f2tf32(p00); u0.y = f2tf32(p01);
            uint2 u1; u1.x = f2tf32(p10); u1.y = f2tf32(p11);
            *reinterpret_cast<uint2*>(&Qs[w*16 + lr    ][nt*8 + 2*lc]) = u0;
            *reinterpret_cast<uint2*>(&Qs[w*16 + lr + 8][nt*8 + 2*lc]) = u1;
        }
        rs0 += __shfl_xor_sync(0xffffffffu, rs0, 1);
        rs0 += __shfl_xor_sync(0xffffffffu, rs0, 2);
        rs1 += __shfl_xor_sync(0xffffffffu, rs1, 1);
        rs1 += __shfl_xor_sync(0xffffffffu, rs1, 2);
        l0 = l0 * cr0 + rs0;
        l1 = l1 * cr1 + rs1;

#pragma unroll
        for (int nt = 0; nt < 8; ++nt) {
            oacc[nt][0] *= cr0; oacc[nt][1] *= cr0;
            oacc[nt][2] *= cr1; oacc[nt][3] *= cr1;
        }
        __syncwarp();

        // O += P @ V  (per warp: 16 x 64, contraction over 64 keys)
#pragma unroll
        for (int ks = 0; ks < 8; ++ks) {
            uint32_t pa[4];
            pa[0] = Qs[w*16 + lr    ][ks*8 + lc    ];
            pa[1] = Qs[w*16 + lr + 8][ks*8 + lc    ];
            pa[2] = Qs[w*16 + lr    ][ks*8 + lc + 4];
            pa[3] = Qs[w*16 + lr + 8][ks*8 + lc + 4];
#pragma unroll
            for (int nt = 0; nt < 8; ++nt) {
                uint32_t bf[2];
                bf[0] = Vs[ks*8 + lc    ][nt*8 + lr];
                bf[1] = Vs[ks*8 + lc + 4][nt*8 + lr];
                mma_tf32(oacc[nt], pa, bf, oacc[nt]);
            }
        }
        __syncthreads();   // K/V consumed before next staging
    }

    float inv0 = 1.f / l0, inv1 = 1.f / l1;
#pragma unroll
    for (int nt = 0; nt < 8; ++nt) {
        int col = hoff + nt*8 + 2*lc;
        float2 o0; o0.x = oacc[nt][0] * inv0; o0.y = oacc[nt][1] * inv0;
        float2 o1; o1.x = oacc[nt][2] * inv1; o1.y = oacc[nt][3] * inv1;
        *reinterpret_cast<float2*>(Og + (rb + q0 + w*16 + lr    ) * 128 + col) = o0;
        *reinterpret_cast<float2*>(Og + (rb + q0 + w*16 + lr + 8) * 128 + col) = o1;
    }
}

// ---------------- final classifier: out = hp @ W_fin + b_fin (CLS=2) ----------------
__global__ __launch_bounds__(256) void final_kernel(
    const float* __restrict__ hp, const float* __restrict__ W,
    const float* __restrict__ bias, float* __restrict__ out)
{
    __shared__ float Ws[256];
    __shared__ float bs[2];
    if (threadIdx.x < 256) Ws[threadIdx.x] = W[threadIdx.x];
    if (threadIdx.x < 2)   bs[threadIdx.x] = bias[threadIdx.x];
    __syncthreads();
    size_t row = (size_t)blockIdx.x * blockDim.x + threadIdx.x;
    const float* hr = hp + row * 128;
    float a0 = bs[0], a1 = bs[1];
#pragma unroll
    for (int k = 0; k < 128; ++k) {
        float hv = hr[k];
        a0 += hv * Ws[2*k+0];
        a1 += hv * Ws[2*k+1];
    }
    out[row*2+0] = a0;
    out[row*2+1] = a1;
}

// ---------------- launch ----------------
extern "C" void kernel_launch(void* const* d_in, const int* in_sizes, int n_in,
                              void* d_out, int out_size) {
    const float* X     = (const float*)d_in[0];
    const float* A     = (const float*)d_in[1];
    const float* T     = (const float*)d_in[2];
    const float* theta = (const float*)d_in[3];
    const float* W_raw = (const float*)d_in[4];
    const float* b_raw = (const float*)d_in[5];
    const float* Wd0   = (const float*)d_in[6];
    const float* bd0   = (const float*)d_in[7];
    const float* Wd1   = (const float*)d_in[8];
    const float* bd1   = (const float*)d_in[9];
    const float* W_fin = (const float*)d_in[10];
    const float* b_fin = (const float*)d_in[11];
    const float* Wq0 = (const float*)d_in[12]; const float* bq0 = (const float*)d_in[13];
    const float* Wk0 = (const float*)d_in[14]; const float* bk0 = (const float*)d_in[15];
    const float* Wv0 = (const float*)d_in[16]; const float* bv0 = (const float*)d_in[17];
    const float* Wo0 = (const float*)d_in[18]; const float* bo0 = (const float*)d_in[19];
    const float* Wq1 = (const float*)d_in[20]; const float* bq1 = (const float*)d_in[21];
    const float* Wk1 = (const float*)d_in[22]; const float* bk1 = (const float*)d_in[23];
    const float* Wv1 = (const float*)d_in[24]; const float* bv1 = (const float*)d_in[25];
    const float* Wo1 = (const float*)d_in[26]; const float* bo1 = (const float*)d_in[27];

    float *Qm, *hp, *h, *z, *qb, *kb, *vb, *ctx;
    cudaGetSymbolAddress((void**)&Qm,  g_Q);
    cudaGetSymbolAddress((void**)&hp,  g_hp);
    cudaGetSymbolAddress((void**)&h,   g_h);
    cudaGetSymbolAddress((void**)&z,   g_z);
    cudaGetSymbolAddress((void**)&qb,  g_qb);
    cudaGetSymbolAddress((void**)&kb,  g_kb);
    cudaGetSymbolAddress((void**)&vb,  g_vb);
    cudaGetSymbolAddress((void**)&ctx, g_ctx);

    const int attn_smem = 256 * 68 * (int)sizeof(uint32_t);  // 69632 B
    cudaFuncSetAttribute(attn_mma_kernel, cudaFuncAttributeMaxDynamicSharedMemorySize, attn_smem);

    const int ggrid = M_ROWS / 128;              // 256 blocks
    dim3 dgrid(NNODE / 128, 1, NB);              // diffusion: per-batch rows
    dim3 attn_grid(NNODE / 128, 2, NB);          // (q-tiles, heads, batch)

    // transition mixing
    theta_softmax_kernel<<<1, 32>>>(theta);
    qmix_kernel<<<2 * 1024 * 1024 / 256, 256>>>(T);

    // raw projection: hp = X @ W_raw + b_raw
    mma_gemm_kernel<<<ggrid, 256>>>(X, X, 64, 64, W_raw, b_raw, nullptr, hp, 0);

    // layer 0 diffusion: h = relu(((Q0⊙A)@X) @ Wd0 + bd0)
    diff_mma_kernel<64><<<dgrid, 256>>>(Qm, A, X, z);
    mma_gemm_kernel<<<ggrid, 256>>>(z, z, 64, 64, Wd0, bd0, nullptr, h, 1);

    // layer 0 attention (concat fused into GEMM A-source)
    mma_gemm_kernel<<<ggrid, 256>>>(h, hp, 128, 256, Wq0, bq0, nullptr, qb, 0);
    mma_gemm_kernel<<<ggrid, 256>>>(h, hp, 128, 256, Wk0, bk0, nullptr, kb, 0);
    mma_gemm_kernel<<<ggrid, 256>>>(h, hp, 128, 256, Wv0, bv0, nullptr, vb, 0);
    attn_mma_kernel<<<attn_grid, 256, attn_smem>>>(qb, kb, vb, ctx);
    mma_gemm_kernel<<<ggrid, 256>>>(ctx, ctx, 128, 128, Wo0, bo0, nullptr, hp, 1);

    // layer 1 diffusion: h = relu(((Q1⊙A)@h) @ Wd1 + bd1)
    diff_mma_kernel<128><<<dgrid, 256>>>(Qm + 1024 * 1024, A, h, z);
    mma_gemm_kernel<<<ggrid, 256>>>(z, z, 128, 128, Wd1, bd1, nullptr, h, 1);

    // layer 1 attention with residual: hp = hp + relu(attn(...))
    mma_gemm_kernel<<<ggrid, 256>>>(h, hp, 128, 256, Wq1, bq1, nullptr, qb, 0);
    mma_gemm_kernel<<<ggrid, 256>>>(h, hp, 128, 256, Wk1, bk1, nullptr, kb, 0);
    mma_gemm_kernel<<<ggrid, 256>>>(h, hp, 128, 256, Wv1, bv1, nullptr, vb, 0);
    attn_mma_kernel<<<attn_grid, 256, attn_smem>>>(qb, kb, vb, ctx);
    mma_gemm_kernel<<<ggrid, 256>>>(ctx, ctx, 128, 128, Wo1, bo1, hp, hp, 1);

    // classifier
    final_kernel<<<M_ROWS / 256, 256>>>(hp, W_fin, b_fin, (float*)d_out);
}

// round 4
// speedup vs baseline: 4.2999x; 1.4283x over previous
#include <cuda_runtime.h>
#include <cuda_fp16.h>
#include <math.h>
#include <stdint.h>

#define M_ROWS 32768          // B*N
#define NB 32
#define NNODE 1024

// ---------------- scratch (device globals, allocation-free) ----------------
__device__ float g_thsm[6];
__device__ float g_Q[2u * 1024u * 1024u];          // mixed transition Q[2][N][N]
__device__ float g_hp [(size_t)M_ROWS * 128];
__device__ float g_h  [(size_t)M_ROWS * 128];
__device__ float g_z  [(size_t)M_ROWS * 128];
__device__ float g_qb [(size_t)M_ROWS * 128];
__device__ float g_kb [(size_t)M_ROWS * 128];
__device__ float g_vb [(size_t)M_ROWS * 128];
__device__ float g_ctx[(size_t)M_ROWS * 128];

// ---------------- helpers ----------------
__device__ __forceinline__ uint32_t f2h2(float a, float b) {
    __half2 h = __floats2half2_rn(a, b);
    return *reinterpret_cast<uint32_t*>(&h);
}

// D(f32) += A(f16 m16 x k16) * B(f16 k16 x n8)
__device__ __forceinline__ void mma_f16(float* d, const uint32_t* a,
                                        const uint32_t* b, const float* c) {
    asm volatile(
        "mma.sync.aligned.m16n8k16.row.col.f32.f16.f16.f32 "
        "{%0,%1,%2,%3}, {%4,%5,%6,%7}, {%8,%9}, {%10,%11,%12,%13};\n"
        : "=f"(d[0]), "=f"(d[1]), "=f"(d[2]), "=f"(d[3])
        : "r"(a[0]), "r"(a[1]), "r"(a[2]), "r"(a[3]),
          "r"(b[0]), "r"(b[1]),
          "f"(c[0]), "f"(c[1]), "f"(c[2]), "f"(c[3]));
}

// ---------------- theta softmax (K=3, 2 layers) ----------------
__global__ void theta_softmax_kernel(const float* __restrict__ th) {
    int l = threadIdx.x;
    if (l < 2) {
        float a = th[l*3+0], b = th[l*3+1], c = th[l*3+2];
        float m = fmaxf(a, fmaxf(b, c));
        float ea = expf(a - m), eb = expf(b - m), ec = expf(c - m);
        float s = ea + eb + ec;
        g_thsm[l*3+0] = ea / s;
        g_thsm[l*3+1] = eb / s;
        g_thsm[l*3+2] = ec / s;
    }
}

// ---------------- Q[l] = sum_k thsm[l,k] * T[l,k] ----------------
__global__ void qmix_kernel(const float* __restrict__ T) {
    size_t i = (size_t)blockIdx.x * 256 + threadIdx.x;
    size_t l  = i >> 20;
    size_t ij = i & 1048575u;
    const float* Tl = T + l * 3u * 1048576u;
    g_Q[i] = g_thsm[l*3+0] * Tl[ij]
           + g_thsm[l*3+1] * Tl[1048576u + ij]
           + g_thsm[l*3+2] * Tl[2u*1048576u + ij];
}

// ============ fp16 MMA dense GEMM: C = [base +] act([A1|A2]@W + bias) ============
// Output width 128. k-step 32, double-buffered half2-packed smem.
__global__ __launch_bounds__(256) void mma_gemm_kernel(
    const float* __restrict__ A1, const float* __restrict__ A2, int K1, int K,
    const float* __restrict__ W, const float* __restrict__ bias,
    const float* __restrict__ base, float* __restrict__ C, int relu)
{
    __shared__ uint32_t As2[2][128][20];   // [m][k2], k2 = 16 half2 per 32-k step
    __shared__ uint32_t Bs2[2][16][136];   // [k2][n] half2 packed along k

    const int tid  = threadIdx.x;
    const int lane = tid & 31;
    const int w    = tid >> 5;
    const int wm   = w & 3;
    const int wn   = w >> 2;
    const int lr   = lane >> 2;
    const int lc   = lane & 3;
    const int row0 = blockIdx.x << 7;

    const int sa_r   = tid >> 1;           // A stage: row 0..127
    const int sa_seg = (tid & 1) << 4;     // A stage: k offset 0 or 16 (floats)

    float4 pa[4];        // A prefetch: 16 floats
    float4 pw0[2], pw1[2];

#define GEMM_LDG(k0)                                                           \
    {                                                                          \
        int kg0 = (k0) + sa_seg;                                               \
        const float* src = (kg0 < K1) ? A1 : A2;                               \
        int kk0    = (kg0 < K1) ? kg0 : (kg0 - K1);                            \
        int stride = (kg0 < K1) ? K1 : (K - K1);                               \
        const float* p = src + (size_t)(row0 + sa_r) * stride + kk0;           \
        _Pragma("unroll")                                                      \
        for (int jj = 0; jj < 4; ++jj)                                         \
            pa[jj] = *reinterpret_cast<const float4*>(p + 4*jj);               \
        _Pragma("unroll")                                                      \
        for (int i = 0; i < 2; ++i) {                                          \
            int idx = tid + i * 256;                                           \
            int k2r = idx >> 5, nq = (idx & 31) << 2;                          \
            pw0[i] = *reinterpret_cast<const float4*>(                         \
                W + (size_t)((k0) + 2*k2r    ) * 128 + nq);                    \
            pw1[i] = *reinterpret_cast<const float4*>(                         \
                W + (size_t)((k0) + 2*k2r + 1) * 128 + nq);                    \
        }                                                                      \
    }

#define GEMM_STS(bufi)                                                        \
    {                                                                          \
        _Pragma("unroll")                                                      \
        for (int jj = 0; jj < 2; ++jj) {                                       \
            uint4 u;                                                           \
            u.x = f2h2(pa[2*jj].x, pa[2*jj].y);                                \
            u.y = f2h2(pa[2*jj].z, pa[2*jj].w);                                \
            u.z = f2h2(pa[2*jj+1].x, pa[2*jj+1].y);                            \
            u.w = f2h2(pa[2*jj+1].z, pa[2*jj+1].w);                            \
            *reinterpret_cast<uint4*>(&As2[bufi][sa_r][(sa_seg>>1) + 4*jj]) = u;\
        }                                                                      \
        _Pragma("unroll")                                                      \
        for (int i = 0; i < 2; ++i) {                                          \
            int idx = tid + i * 256;                                           \
            int k2r = idx >> 5, nq = (idx & 31) << 2;                          \
            uint4 u;                                                           \
            u.x = f2h2(pw0[i].x, pw1[i].x);                                    \
            u.y = f2h2(pw0[i].y, pw1[i].y);                                    \
            u.z = f2h2(pw0[i].z, pw1[i].z);                                    \
            u.w = f2h2(pw0[i].w, pw1[i].w);                                    \
            *reinterpret_cast<uint4*>(&Bs2[bufi][k2r][nq]) = u;                \
        }                                                                      \
    }

    float acc[2][8][4];
#pragma unroll
    for (int mt = 0; mt < 2; ++mt)
#pragma unroll
        for (int nt = 0; nt < 8; ++nt)
#pragma unroll
            for (int i = 0; i < 4; ++i) acc[mt][nt][i] = 0.f;

    GEMM_LDG(0);
    GEMM_STS(0);
    __syncthreads();

    int buf = 0;
    for (int k0 = 0; k0 < K; k0 += 32) {
        const bool has_next = (k0 + 32 < K);
        if (has_next) GEMM_LDG(k0 + 32);

#pragma unroll
        for (int s = 0; s < 2; ++s) {
            uint32_t a[2][4], b[8][2];
#pragma unroll
            for (int mt = 0; mt < 2; ++mt) {
                int rm = wm*32 + mt*16 + lr;
                a[mt][0] = As2[buf][rm    ][s*8 + lc    ];
                a[mt][1] = As2[buf][rm + 8][s*8 + lc    ];
                a[mt][2] = As2[buf][rm    ][s*8 + lc + 4];
                a[mt][3] = As2[buf][rm + 8][s*8 + lc + 4];
            }
#pragma unroll
            for (int nt = 0; nt < 8; ++nt) {
                int nb = wn*64 + nt*8 + lr;
                b[nt][0] = Bs2[buf][s*8 + lc    ][nb];
                b[nt][1] = Bs2[buf][s*8 + lc + 4][nb];
            }
#pragma unroll
            for (int mt = 0; mt < 2; ++mt)
#pragma unroll
                for (int nt = 0; nt < 8; ++nt)
                    mma_f16(acc[mt][nt], a[mt], b[nt], acc[mt][nt]);
        }

        if (has_next) GEMM_STS(buf ^ 1);
        __syncthreads();
        buf ^= 1;
    }

#pragma unroll
    for (int mt = 0; mt < 2; ++mt) {
#pragma unroll
        for (int nt = 0; nt < 8; ++nt) {
            int col = wn*64 + nt*8 + 2*lc;
            float b0 = bias[col], b1 = bias[col+1];
#pragma unroll
            for (int half = 0; half < 2; ++half) {
                int row = row0 + wm*32 + mt*16 + lr + half*8;
                float v0 = acc[mt][nt][half*2+0] + b0;
                float v1 = acc[mt][nt][half*2+1] + b1;
                if (relu) { v0 = fmaxf(v0, 0.f); v1 = fmaxf(v1, 0.f); }
                if (base) {
                    const float2 bv = *reinterpret_cast<const float2*>(
                        base + (size_t)row * 128 + col);
                    v0 += bv.x; v1 += bv.y;
                }
                float2 o; o.x = v0; o.y = v1;
                *reinterpret_cast<float2*>(C + (size_t)row * 128 + col) = o;
            }
        }
    }
#undef GEMM_LDG
#undef GEMM_STS
}

// ====== fp16 MMA masked diffusion GEMM: Z[b] = (Qm ⊙ Adj[b]) @ Hin[b] ======
template<int BN>
__global__ __launch_bounds__(256) void diff_mma_kernel(
    const float* __restrict__ Qm, const float* __restrict__ Adj,
    const float* __restrict__ Hin, float* __restrict__ Z)
{
    constexpr int WN = BN / 2;     // 32 or 64
    constexpr int NT = WN / 8;     // 4 or 8
    constexpr int NI = BN / 64;    // B staging iterations

    __shared__ uint32_t As2[2][128][20];
    __shared__ uint32_t Bs2[2][16][BN + 8];

    const int tid  = threadIdx.x;
    const int lane = tid & 31;
    const int w    = tid >> 5;
    const int wm   = w & 3;
    const int wn   = w >> 2;
    const int lr   = lane >> 2;
    const int lc   = lane & 3;
    const int b    = blockIdx.z;
    const int i0   = blockIdx.x << 7;
    const size_t adjb = (size_t)b * NNODE * NNODE;
    const size_t hb   = (size_t)b * NNODE * BN;

    const int sa_r   = tid >> 1;
    const int sa_seg = (tid & 1) << 4;

    float4 pq[4], pv[4];
    float4 ph0[NI], ph1[NI];

#define DIFF_LDG(j0)                                                           \
    {                                                                          \
        size_t off = (size_t)(i0 + sa_r) * NNODE + (j0) + sa_seg;              \
        _Pragma("unroll")                                                      \
        for (int jj = 0; jj < 4; ++jj) {                                       \
            pq[jj] = *reinterpret_cast<const float4*>(Qm + off + 4*jj);        \
            pv[jj] = *reinterpret_cast<const float4*>(Adj + adjb + off + 4*jj);\
        }                                                                      \
        _Pragma("unroll")                                                      \
        for (int i = 0; i < NI; ++i) {                                         \
            int idx = tid + i * 256;                                           \
            int k2r = idx / (BN/4), nq = (idx % (BN/4)) << 2;                  \
            ph0[i] = *reinterpret_cast<const float4*>(                         \
                Hin + hb + (size_t)((j0) + 2*k2r    ) * BN + nq);              \
            ph1[i] = *reinterpret_cast<const float4*>(                         \
                Hin + hb + (size_t)((j0) + 2*k2r + 1) * BN + nq);              \
        }                                                                      \
    }

#define DIFF_STS(bufi)                                                        \
    {                                                                          \
        _Pragma("unroll")                                                      \
        for (int jj = 0; jj < 2; ++jj) {                                       \
            float4 q0 = pq[2*jj],   a0 = pv[2*jj];                             \
            float4 q1 = pq[2*jj+1], a1 = pv[2*jj+1];                           \
            uint4 u;                                                           \
            u.x = f2h2(q0.x*a0.x, q0.y*a0.y);                                  \
            u.y = f2h2(q0.z*a0.z, q0.w*a0.w);                                  \
            u.z = f2h2(q1.x*a1.x, q1.y*a1.y);                                  \
            u.w = f2h2(q1.z*a1.z, q1.w*a1.w);                                  \
            *reinterpret_cast<uint4*>(&As2[bufi][sa_r][(sa_seg>>1) + 4*jj]) = u;\
        }                                                                      \
        _Pragma("unroll")                                                      \
        for (int i = 0; i < NI; ++i) {                                         \
            int idx = tid + i * 256;                                           \
            int k2r = idx / (BN/4), nq = (idx % (BN/4)) << 2;                  \
            uint4 u;                                                           \
            u.x = f2h2(ph0[i].x, ph1[i].x);                                    \
            u.y = f2h2(ph0[i].y, ph1[i].y);                                    \
            u.z = f2h2(ph0[i].z, ph1[i].z);                                    \
            u.w = f2h2(ph0[i].w, ph1[i].w);                                    \
            *reinterpret_cast<uint4*>(&Bs2[bufi][k2r][nq]) = u;                \
        }                                                                      \
    }

    float acc[2][NT][4];
#pragma unroll
    for (int mt = 0; mt < 2; ++mt)
#pragma unroll
        for (int nt = 0; nt < NT; ++nt)
#pragma unroll
            for (int i = 0; i < 4; ++i) acc[mt][nt][i] = 0.f;

    DIFF_LDG(0);
    DIFF_STS(0);
    __syncthreads();

    int buf = 0;
    for (int j0 = 0; j0 < NNODE; j0 += 32) {
        const bool has_next = (j0 + 32 < NNODE);
        if (has_next) DIFF_LDG(j0 + 32);

#pragma unroll
        for (int s = 0; s < 2; ++s) {
            uint32_t a[2][4], bf[NT][2];
#pragma unroll
            for (int mt = 0; mt < 2; ++mt) {
                int rm = wm*32 + mt*16 + lr;
                a[mt][0] = As2[buf][rm    ][s*8 + lc    ];
                a[mt][1] = As2[buf][rm + 8][s*8 + lc    ];
                a[mt][2] = As2[buf][rm    ][s*8 + lc + 4];
                a[mt][3] = As2[buf][rm + 8][s*8 + lc + 4];
            }
#pragma unroll
            for (int nt = 0; nt < NT; ++nt) {
                int nb = wn*WN + nt*8 + lr;
                bf[nt][0] = Bs2[buf][s*8 + lc    ][nb];
                bf[nt][1] = Bs2[buf][s*8 + lc + 4][nb];
            }
#pragma unroll
            for (int mt = 0; mt < 2; ++mt)
#pragma unroll
                for (int nt = 0; nt < NT; ++nt)
                    mma_f16(acc[mt][nt], a[mt], bf[nt], acc[mt][nt]);
        }

        if (has_next) DIFF_STS(buf ^ 1);
        __syncthreads();
        buf ^= 1;
    }

#pragma unroll
    for (int mt = 0; mt < 2; ++mt) {
#pragma unroll
        for (int nt = 0; nt < NT; ++nt) {
            int col = wn*WN + nt*8 + 2*lc;
#pragma unroll
            for (int half = 0; half < 2; ++half) {
                int row = i0 + wm*32 + mt*16 + lr + half*8;
                float2 o;
                o.x = acc[mt][nt][half*2+0];
                o.y = acc[mt][nt][half*2+1];
                *reinterpret_cast<float2*>(Z + hb + (size_t)row * BN + col) = o;
            }
        }
    }
#undef DIFF_LDG
#undef DIFF_STS
}

// ========== fp16 MMA flash attention: H=2 heads, d=64, N=1024 ==========
// 256 threads, 128 queries/block; warp w owns query rows w*16..w*16+15.
// Softmax in exp2 domain (Q pre-scaled by log2(e)/8).
__global__ __launch_bounds__(256) void attn_mma_kernel(
    const float* __restrict__ Qg, const float* __restrict__ Kg,
    const float* __restrict__ Vg, float* __restrict__ Og)
{
    __shared__ uint32_t Ps2[128][36];   // Q staging, then P (warp-local rows)
    __shared__ uint32_t Ks2[64][36];    // K packed along d
    __shared__ uint32_t Vs2[32][72];    // V packed along key

    const int tid  = threadIdx.x;
    const int lane = tid & 31;
    const int w    = tid >> 5;
    const int lr   = lane >> 2;
    const int lc   = lane & 3;
    const int b    = blockIdx.z, h = blockIdx.y;
    const int q0   = blockIdx.x << 7;
    const size_t rb = (size_t)b * NNODE;
    const int hoff = h * 64;
    const float SC = 0.125f * 1.4426950408889634f;   // 1/sqrt(64) * log2(e)

    // --- stage this warp's Q rows (warp-local) ---
    {
        int r   = w*16 + (lane >> 1);
        int seg = (lane & 1) * 32;                    // floats
        const float* p = Qg + (rb + q0 + r) * 128 + hoff + seg;
#pragma unroll
        for (int jj = 0; jj < 4; ++jj) {
            float4 v0 = *reinterpret_cast<const float4*>(p + 8*jj);
            float4 v1 = *reinterpret_cast<const float4*>(p + 8*jj + 4);
            uint4 u;
            u.x = f2h2(v0.x*SC, v0.y*SC);
            u.y = f2h2(v0.z*SC, v0.w*SC);
            u.z = f2h2(v1.x*SC, v1.y*SC);
            u.w = f2h2(v1.z*SC, v1.w*SC);
            *reinterpret_cast<uint4*>(&Ps2[r][(seg>>1) + 4*jj]) = u;
        }
    }
    __syncwarp();

    uint32_t qa[4][4];
#pragma unroll
    for (int ks = 0; ks < 4; ++ks) {
        qa[ks][0] = Ps2[w*16 + lr    ][ks*8 + lc    ];
        qa[ks][1] = Ps2[w*16 + lr + 8][ks*8 + lc    ];
        qa[ks][2] = Ps2[w*16 + lr    ][ks*8 + lc + 4];
        qa[ks][3] = Ps2[w*16 + lr + 8][ks*8 + lc + 4];
    }

    float m0 = -1e30f, m1 = -1e30f, l0 = 0.f, l1 = 0.f;
    float oacc[8][4];
#pragma unroll
    for (int nt = 0; nt < 8; ++nt)
#pragma unroll
        for (int i = 0; i < 4; ++i) oacc[nt][i] = 0.f;

    float4 pk[4], pv0[2], pv1[2];
    const int kr   = tid >> 2;
    const int kseg = (tid & 3) << 4;    // floats

#define ATTN_LDG(j0)                                                           \
    {                                                                          \
        const float* p = Kg + (rb + (j0) + kr) * 128 + hoff + kseg;            \
        _Pragma("unroll")                                                      \
        for (int jj = 0; jj < 4; ++jj)                                         \
            pk[jj] = *reinterpret_cast<const float4*>(p + 4*jj);               \
        _Pragma("unroll")                                                      \
        for (int i = 0; i < 2; ++i) {                                          \
            int idx = tid + i * 256;                                           \
            int k2r = idx >> 4, dq = (idx & 15) << 2;                          \
            pv0[i] = *reinterpret_cast<const float4*>(                         \
                Vg + (rb + (j0) + 2*k2r    ) * 128 + hoff + dq);               \
            pv1[i] = *reinterpret_cast<const float4*>(                         \
                Vg + (rb + (j0) + 2*k2r + 1) * 128 + hoff + dq);               \
        }                                                                      \
    }

#define ATTN_STS()                                                            \
    {                                                                          \
        _Pragma("unroll")                                                      \
        for (int jj = 0; jj < 2; ++jj) {                                       \
            uint4 u;                                                           \
            u.x = f2h2(pk[2*jj].x, pk[2*jj].y);                                \
            u.y = f2h2(pk[2*jj].z, pk[2*jj].w);                                \
            u.z = f2h2(pk[2*jj+1].x, pk[2*jj+1].y);                            \
            u.w = f2h2(pk[2*jj+1].z, pk[2*jj+1].w);                            \
            *reinterpret_cast<uint4*>(&Ks2[kr][(kseg>>1) + 4*jj]) = u;         \
        }                                                                      \
        _Pragma("unroll")                                                      \
        for (int i = 0; i < 2; ++i) {                                          \
            int idx = tid + i * 256;                                           \
            int k2r = idx >> 4, dq = (idx & 15) << 2;                          \
            uint4 u;                                                           \
            u.x = f2h2(pv0[i].x, pv1[i].x);                                    \
            u.y = f2h2(pv0[i].y, pv1[i].y);                                    \
            u.z = f2h2(pv0[i].z, pv1[i].z);                                    \
            u.w = f2h2(pv0[i].w, pv1[i].w);                                    \
            *reinterpret_cast<uint4*>(&Vs2[k2r][dq]) = u;                      \
        }                                                                      \
    }

    ATTN_LDG(0);
    ATTN_STS();
    __syncthreads();

    for (int c = 0; c < NNODE/64; ++c) {
        // S = Q @ K^T  (warp: 16 x 64)
        float sacc[8][4];
#pragma unroll
        for (int nt = 0; nt < 8; ++nt)
#pragma unroll
            for (int i = 0; i < 4; ++i) sacc[nt][i] = 0.f;
#pragma unroll
        for (int ks = 0; ks < 4; ++ks) {
#pragma unroll
            for (int nt = 0; nt < 8; ++nt) {
                uint32_t bf[2];
                bf[0] = Ks2[nt*8 + lr][ks*8 + lc    ];
                bf[1] = Ks2[nt*8 + lr][ks*8 + lc + 4];
                mma_f16(sacc[nt], qa[ks], bf, sacc[nt]);
            }
        }

        // prefetch next chunk while softmax+PV run
        const bool has_next = (c + 1 < NNODE/64);
        if (has_next) ATTN_LDG((c + 1) * 64);

        // online softmax (exp2 domain)
        float rmax0 = -1e30f, rmax1 = -1e30f;
#pragma unroll
        for (int nt = 0; nt < 8; ++nt) {
            rmax0 = fmaxf(rmax0, fmaxf(sacc[nt][0], sacc[nt][1]));
            rmax1 = fmaxf(rmax1, fmaxf(sacc[nt][2], sacc[nt][3]));
        }
        rmax0 = fmaxf(rmax0, __shfl_xor_sync(0xffffffffu, rmax0, 1));
        rmax0 = fmaxf(rmax0, __shfl_xor_sync(0xffffffffu, rmax0, 2));
        rmax1 = fmaxf(rmax1, __shfl_xor_sync(0xffffffffu, rmax1, 1));
        rmax1 = fmaxf(rmax1, __shfl_xor_sync(0xffffffffu, rmax1, 2));

        float mn0 = fmaxf(m0, rmax0), mn1 = fmaxf(m1, rmax1);
        float cr0 = exp2f(m0 - mn0), cr1 = exp2f(m1 - mn1);
        m0 = mn0; m1 = mn1;

        float rs0 = 0.f, rs1 = 0.f;
#pragma unroll
        for (int nt = 0; nt < 8; ++nt) {
            float p00 = exp2f(sacc[nt][0] - mn0);
            float p01 = exp2f(sacc[nt][1] - mn0);
            float p10 = exp2f(sacc[nt][2] - mn1);
            float p11 = exp2f(sacc[nt][3] - mn1);
            __half2 h0 = __floats2half2_rn(p00, p01);
            __half2 h1 = __floats2half2_rn(p10, p11);
            float2 f0 = __half22float2(h0);
            float2 f1 = __half22float2(h1);
            rs0 += f0.x + f0.y;
            rs1 += f1.x + f1.y;
            Ps2[w*16 + lr    ][nt*4 + lc] = *reinterpret_cast<uint32_t*>(&h0);
            Ps2[w*16 + lr + 8][nt*4 + lc] = *reinterpret_cast<uint32_t*>(&h1);
        }
        rs0 += __shfl_xor_sync(0xffffffffu, rs0, 1);
        rs0 += __shfl_xor_sync(0xffffffffu, rs0, 2);
        rs1 += __shfl_xor_sync(0xffffffffu, rs1, 1);
        rs1 += __shfl_xor_sync(0xffffffffu, rs1, 2);
        l0 = l0 * cr0 + rs0;
        l1 = l1 * cr1 + rs1;

#pragma unroll
        for (int nt = 0; nt < 8; ++nt) {
            oacc[nt][0] *= cr0; oacc[nt][1] *= cr0;
            oacc[nt][2] *= cr1; oacc[nt][3] *= cr1;
        }
        __syncwarp();

        // O += P @ V
#pragma unroll
        for (int ks = 0; ks < 4; ++ks) {
            uint32_t pa[4];
            pa[0] = Ps2[w*16 + lr    ][ks*8 + lc    ];
            pa[1] = Ps2[w*16 + lr + 8][ks*8 + lc    ];
            pa[2] = Ps2[w*16 + lr    ][ks*8 + lc + 4];
            pa[3] = Ps2[w*16 + lr + 8][ks*8 + lc + 4];
#pragma unroll
            for (int nt = 0; nt < 8; ++nt) {
                uint32_t bf[2];
                bf[0] = Vs2[ks*8 + lc    ][nt*8 + lr];
                bf[1] = Vs2[ks*8 + lc + 4][nt*8 + lr];
                mma_f16(oacc[nt], pa, bf, oacc[nt]);
            }
        }

        __syncthreads();           // all warps done reading K/V
        if (has_next) {
            ATTN_STS();
            __syncthreads();
        }
    }

    float inv0 = 1.f / l0, inv1 = 1.f / l1;
#pragma unroll
    for (int nt = 0; nt < 8; ++nt) {
        int col = hoff + nt*8 + 2*lc;
        float2 o0; o0.x = oacc[nt][0] * inv0; o0.y = oacc[nt][1] * inv0;
        float2 o1; o1.x = oacc[nt][2] * inv1; o1.y = oacc[nt][3] * inv1;
        *reinterpret_cast<float2*>(Og + (rb + q0 + w*16 + lr    ) * 128 + col) = o0;
        *reinterpret_cast<float2*>(Og + (rb + q0 + w*16 + lr + 8) * 128 + col) = o1;
    }
#undef ATTN_LDG
#undef ATTN_STS
}

// ---------------- final classifier: out = hp @ W_fin + b_fin (CLS=2) ----------------
__global__ __launch_bounds__(256) void final_kernel(
    const float* __restrict__ hp, const float* __restrict__ W,
    const float* __restrict__ bias, float* __restrict__ out)
{
    __shared__ float Ws[256];
    __shared__ float bs[2];
    if (threadIdx.x < 256) Ws[threadIdx.x] = W[threadIdx.x];
    if (threadIdx.x < 2)   bs[threadIdx.x] = bias[threadIdx.x];
    __syncthreads();
    size_t row = (size_t)blockIdx.x * blockDim.x + threadIdx.x;
    const float* hr = hp + row * 128;
    float a0 = bs[0], a1 = bs[1];
#pragma unroll
    for (int k = 0; k < 128; ++k) {
        float hv = hr[k];
        a0 += hv * Ws[2*k+0];
        a1 += hv * Ws[2*k+1];
    }
    out[row*2+0] = a0;
    out[row*2+1] = a1;
}

// ---------------- launch ----------------
extern "C" void kernel_launch(void* const* d_in, const int* in_sizes, int n_in,
                              void* d_out, int out_size) {
    const float* X     = (const float*)d_in[0];
    const float* A     = (const float*)d_in[1];
    const float* T     = (const float*)d_in[2];
    const float* theta = (const float*)d_in[3];
    const float* W_raw = (const float*)d_in[4];
    const float* b_raw = (const float*)d_in[5];
    const float* Wd0   = (const float*)d_in[6];
    const float* bd0   = (const float*)d_in[7];
    const float* Wd1   = (const float*)d_in[8];
    const float* bd1   = (const float*)d_in[9];
    const float* W_fin = (const float*)d_in[10];
    const float* b_fin = (const float*)d_in[11];
    const float* Wq0 = (const float*)d_in[12]; const float* bq0 = (const float*)d_in[13];
    const float* Wk0 = (const float*)d_in[14]; const float* bk0 = (const float*)d_in[15];
    const float* Wv0 = (const float*)d_in[16]; const float* bv0 = (const float*)d_in[17];
    const float* Wo0 = (const float*)d_in[18]; const float* bo0 = (const float*)d_in[19];
    const float* Wq1 = (const float*)d_in[20]; const float* bq1 = (const float*)d_in[21];
    const float* Wk1 = (const float*)d_in[22]; const float* bk1 = (const float*)d_in[23];
    const float* Wv1 = (const float*)d_in[24]; const float* bv1 = (const float*)d_in[25];
    const float* Wo1 = (const float*)d_in[26]; const float* bo1 = (const float*)d_in[27];

    float *Qm, *hp, *h, *z, *qb, *kb, *vb, *ctx;
    cudaGetSymbolAddress((void**)&Qm,  g_Q);
    cudaGetSymbolAddress((void**)&hp,  g_hp);
    cudaGetSymbolAddress((void**)&h,   g_h);
    cudaGetSymbolAddress((void**)&z,   g_z);
    cudaGetSymbolAddress((void**)&qb,  g_qb);
    cudaGetSymbolAddress((void**)&kb,  g_kb);
    cudaGetSymbolAddress((void**)&vb,  g_vb);
    cudaGetSymbolAddress((void**)&ctx, g_ctx);

    const int ggrid = M_ROWS / 128;              // 256 blocks
    dim3 dgrid(NNODE / 128, 1, NB);
    dim3 attn_grid(NNODE / 128, 2, NB);

    theta_softmax_kernel<<<1, 32>>>(theta);
    qmix_kernel<<<2 * 1024 * 1024 / 256, 256>>>(T);

    // raw projection
    mma_gemm_kernel<<<ggrid, 256>>>(X, X, 64, 64, W_raw, b_raw, nullptr, hp, 0);

    // layer 0 diffusion
    diff_mma_kernel<64><<<dgrid, 256>>>(Qm, A, X, z);
    mma_gemm_kernel<<<ggrid, 256>>>(z, z, 64, 64, Wd0, bd0, nullptr, h, 1);

    // layer 0 attention
    mma_gemm_kernel<<<ggrid, 256>>>(h, hp, 128, 256, Wq0, bq0, nullptr, qb, 0);
    mma_gemm_kernel<<<ggrid, 256>>>(h, hp, 128, 256, Wk0, bk0, nullptr, kb, 0);
    mma_gemm_kernel<<<ggrid, 256>>>(h, hp, 128, 256, Wv0, bv0, nullptr, vb, 0);
    attn_mma_kernel<<<attn_grid, 256>>>(qb, kb, vb, ctx);
    mma_gemm_kernel<<<ggrid, 256>>>(ctx, ctx, 128, 128, Wo0, bo0, nullptr, hp, 1);

    // layer 1 diffusion
    diff_mma_kernel<128><<<dgrid, 256>>>(Qm + 1024 * 1024, A, h, z);
    mma_gemm_kernel<<<ggrid, 256>>>(z, z, 128, 128, Wd1, bd1, nullptr, h, 1);

    // layer 1 attention with residual
    mma_gemm_kernel<<<ggrid, 256>>>(h, hp, 128, 256, Wq1, bq1, nullptr, qb, 0);
    mma_gemm_kernel<<<ggrid, 256>>>(h, hp, 128, 256, Wk1, bk1, nullptr, kb, 0);
    mma_gemm_kernel<<<ggrid, 256>>>(h, hp, 128, 256, Wv1, bv1, nullptr, vb, 0);
    attn_mma_kernel<<<attn_grid, 256>>>(qb, kb, vb, ctx);
    mma_gemm_kernel<<<ggrid, 256>>>(ctx, ctx, 128, 128, Wo1, bo1, hp, hp, 1);

    // classifier
    final_kernel<<<M_ROWS / 256, 256>>>(hp, W_fin, b_fin, (float*)d_out);
}

// round 6
// speedup vs baseline: 5.3559x; 1.2456x over previous
#include <cuda_runtime.h>
#include <cuda_fp16.h>
#include <math.h>
#include <stdint.h>

#define M_ROWS 32768          // B*N
#define NB 32
#define NNODE 1024
#define NN2 (1024u * 1024u)

// ---------------- scratch (device globals, allocation-free) ----------------
__device__ float  g_thsm[6];
__device__ float  g_Q[2u * NN2];                       // mixed transition fp32
__device__ __half g_P0[(size_t)NB * NN2];              // half(Q0 ⊙ A)
__device__ __half g_P1[(size_t)NB * NN2];              // half(Q1 ⊙ A)
__device__ __half g_X16[(size_t)M_ROWS * 64];
__device__ __half g_hp [(size_t)M_ROWS * 128];
__device__ __half g_h  [(size_t)M_ROWS * 128];
__device__ __half g_z  [(size_t)M_ROWS * 128];
__device__ __half g_qb [(size_t)M_ROWS * 128];
__device__ __half g_kb [(size_t)M_ROWS * 128];
__device__ __half g_vb [(size_t)M_ROWS * 128];
__device__ __half g_ctx[(size_t)M_ROWS * 128];

// ---------------- helpers ----------------
__device__ __forceinline__ uint32_t f2h2(float a, float b) {
    __half2 h = __floats2half2_rn(a, b);
    return *reinterpret_cast<uint32_t*>(&h);
}
__device__ __forceinline__ uint32_t h2bits(__half2 h) {
    return *reinterpret_cast<uint32_t*>(&h);
}

__device__ __forceinline__ void mma_f16(float* d, const uint32_t* a,
                                        const uint32_t* b, const float* c) {
    asm volatile(
        "mma.sync.aligned.m16n8k16.row.col.f32.f16.f16.f32 "
        "{%0,%1,%2,%3}, {%4,%5,%6,%7}, {%8,%9}, {%10,%11,%12,%13};\n"
        : "=f"(d[0]), "=f"(d[1]), "=f"(d[2]), "=f"(d[3])
        : "r"(a[0]), "r"(a[1]), "r"(a[2]), "r"(a[3]),
          "r"(b[0]), "r"(b[1]),
          "f"(c[0]), "f"(c[1]), "f"(c[2]), "f"(c[3]));
}

// ---------------- theta softmax ----------------
__global__ void theta_softmax_kernel(const float* __restrict__ th) {
    int l = threadIdx.x;
    if (l < 2) {
        float a = th[l*3+0], b = th[l*3+1], c = th[l*3+2];
        float m = fmaxf(a, fmaxf(b, c));
        float ea = expf(a - m), eb = expf(b - m), ec = expf(c - m);
        float s = ea + eb + ec;
        g_thsm[l*3+0] = ea / s;
        g_thsm[l*3+1] = eb / s;
        g_thsm[l*3+2] = ec / s;
    }
}

// ---------------- Q[l] = sum_k thsm[l,k] * T[l,k] ----------------
__global__ void qmix_kernel(const float* __restrict__ T) {
    size_t i = (size_t)blockIdx.x * 256 + threadIdx.x;
    size_t l  = i >> 20;
    size_t ij = i & (NN2 - 1);
    const float* Tl = T + l * 3u * NN2;
    g_Q[i] = g_thsm[l*3+0] * Tl[ij]
           + g_thsm[l*3+1] * Tl[NN2 + ij]
           + g_thsm[l*3+2] * Tl[2u*NN2 + ij];
}

// ---------------- P16[l] = half(Q[l] ⊙ A), A read once ----------------
__global__ void pmul_kernel(const float* __restrict__ A) {
    size_t i  = ((size_t)blockIdx.x * 256 + threadIdx.x) * 4;
    size_t ij = i & (NN2 - 1);
    float4 a  = *reinterpret_cast<const float4*>(A + i);
    float4 q0 = *reinterpret_cast<const float4*>(g_Q + ij);
    float4 q1 = *reinterpret_cast<const float4*>(g_Q + NN2 + ij);
    uint2 u0, u1;
    u0.x = f2h2(q0.x*a.x, q0.y*a.y);
    u0.y = f2h2(q0.z*a.z, q0.w*a.w);
    u1.x = f2h2(q1.x*a.x, q1.y*a.y);
    u1.y = f2h2(q1.z*a.z, q1.w*a.w);
    *reinterpret_cast<uint2*>(g_P0 + i) = u0;
    *reinterpret_cast<uint2*>(g_P1 + i) = u1;
}

// ---------------- fp32 -> fp16 cast (for X) ----------------
__global__ void tohalf_kernel(const float* __restrict__ x, __half* __restrict__ o) {
    size_t i = ((size_t)blockIdx.x * 256 + threadIdx.x) * 4;
    float4 v = *reinterpret_cast<const float4*>(x + i);
    uint2 u;
    u.x = f2h2(v.x, v.y);
    u.y = f2h2(v.z, v.w);
    *reinterpret_cast<uint2*>(o + i) = u;
}

// ============ fp16 GEMM: C16 = [base16 +] act([A1|A2]@W + bias) ============
// A fp16 [M,K] (concat of A1[:, :K1], A2[:, :K-K1]); W fp32 [K,128]; C fp16 [M,128].
__global__ __launch_bounds__(256) void hgemm_kernel(
    const __half* __restrict__ A1, const __half* __restrict__ A2, int K1, int K,
    const float* __restrict__ W, const float* __restrict__ bias,
    const __half* __restrict__ base, __half* __restrict__ C, int relu)
{
    __shared__ uint32_t As2[2][128][20];   // [m][k2] half2 pairs along k
    __shared__ uint32_t Bs2[2][16][136];   // [k2][n]

    const int tid  = threadIdx.x;
    const int lane = tid & 31;
    const int w    = tid >> 5;
    const int wm   = w & 3;
    const int wn   = w >> 2;
    const int lr   = lane >> 2;
    const int lc   = lane & 3;
    const int row0 = blockIdx.x << 7;

    const int sa_r   = tid >> 1;
    const int sa_k16 = (tid & 1) << 4;     // half offset 0 / 16

    uint4 pa0, pa1;
    float4 pw0[2], pw1[2];

#define GEMM_LDG(k0)                                                           \
    {                                                                          \
        int kg = (k0) + sa_k16;                                                \
        const __half* src = (kg < K1) ? A1 : A2;                               \
        int kk     = (kg < K1) ? kg : (kg - K1);                               \
        int stride = (kg < K1) ? K1 : (K - K1);                                \
        const __half* p = src + (size_t)(row0 + sa_r) * stride + kk;           \
        pa0 = *reinterpret_cast<const uint4*>(p);                              \
        pa1 = *reinterpret_cast<const uint4*>(p + 8);                          \
        _Pragma("unroll")                                                      \
        for (int i = 0; i < 2; ++i) {                                          \
            int idx = tid + i * 256;                                           \
            int k2r = idx >> 5, nq = (idx & 31) << 2;                          \
            pw0[i] = *reinterpret_cast<const float4*>(                         \
                W + (size_t)((k0) + 2*k2r    ) * 128 + nq);                    \
            pw1[i] = *reinterpret_cast<const float4*>(                         \
                W + (size_t)((k0) + 2*k2r + 1) * 128 + nq);                    \
        }                                                                      \
    }

#define GEMM_STS(bufi)                                                        \
    {                                                                          \
        *reinterpret_cast<uint4*>(&As2[bufi][sa_r][(sa_k16>>1)    ]) = pa0;    \
        *reinterpret_cast<uint4*>(&As2[bufi][sa_r][(sa_k16>>1) + 4]) = pa1;    \
        _Pragma("unroll")                                                      \
        for (int i = 0; i < 2; ++i) {                                          \
            int idx = tid + i * 256;                                           \
            int k2r = idx >> 5, nq = (idx & 31) << 2;                          \
            uint4 u;                                                           \
            u.x = f2h2(pw0[i].x, pw1[i].x);                                    \
            u.y = f2h2(pw0[i].y, pw1[i].y);                                    \
            u.z = f2h2(pw0[i].z, pw1[i].z);                                    \
            u.w = f2h2(pw0[i].w, pw1[i].w);                                    \
            *reinterpret_cast<uint4*>(&Bs2[bufi][k2r][nq]) = u;                \
        }                                                                      \
    }

    float acc[2][8][4];
#pragma unroll
    for (int mt = 0; mt < 2; ++mt)
#pragma unroll
        for (int nt = 0; nt < 8; ++nt)
#pragma unroll
            for (int i = 0; i < 4; ++i) acc[mt][nt][i] = 0.f;

    GEMM_LDG(0);
    GEMM_STS(0);
    __syncthreads();

    int buf = 0;
    for (int k0 = 0; k0 < K; k0 += 32) {
        const bool has_next = (k0 + 32 < K);
        if (has_next) GEMM_LDG(k0 + 32);

#pragma unroll
        for (int s = 0; s < 2; ++s) {
            uint32_t a[2][4], b[8][2];
#pragma unroll
            for (int mt = 0; mt < 2; ++mt) {
                int rm = wm*32 + mt*16 + lr;
                a[mt][0] = As2[buf][rm    ][s*8 + lc    ];
                a[mt][1] = As2[buf][rm + 8][s*8 + lc    ];
                a[mt][2] = As2[buf][rm    ][s*8 + lc + 4];
                a[mt][3] = As2[buf][rm + 8][s*8 + lc + 4];
            }
#pragma unroll
            for (int nt = 0; nt < 8; ++nt) {
                int nb = wn*64 + nt*8 + lr;
                b[nt][0] = Bs2[buf][s*8 + lc    ][nb];
                b[nt][1] = Bs2[buf][s*8 + lc + 4][nb];
            }
#pragma unroll
            for (int mt = 0; mt < 2; ++mt)
#pragma unroll
                for (int nt = 0; nt < 8; ++nt)
                    mma_f16(acc[mt][nt], a[mt], b[nt], acc[mt][nt]);
        }

        if (has_next) GEMM_STS(buf ^ 1);
        __syncthreads();
        buf ^= 1;
    }

#pragma unroll
    for (int mt = 0; mt < 2; ++mt) {
#pragma unroll
        for (int nt = 0; nt < 8; ++nt) {
            int col = wn*64 + nt*8 + 2*lc;
            float b0 = bias[col], b1 = bias[col+1];
#pragma unroll
            for (int half = 0; half < 2; ++half) {
                int row = row0 + wm*32 + mt*16 + lr + half*8;
                float v0 = acc[mt][nt][half*2+0] + b0;
                float v1 = acc[mt][nt][half*2+1] + b1;
                if (relu) { v0 = fmaxf(v0, 0.f); v1 = fmaxf(v1, 0.f); }
                if (base) {
                    __half2 bh = *reinterpret_cast<const __half2*>(
                        base + (size_t)row * 128 + col);
                    float2 bf = __half22float2(bh);
                    v0 += bf.x; v1 += bf.y;
                }
                *reinterpret_cast<uint32_t*>(C + (size_t)row * 128 + col) =
                    f2h2(v0, v1);
            }
        }
    }
#undef GEMM_LDG
#undef GEMM_STS
}

// ====== fp16 diffusion GEMM: Z16[b] = P16[b] @ H16[b] ======
// P16 [N,N] fp16 row-major; H16 [N,BN] fp16; Z16 [N,BN] fp16.
template<int BN>
__global__ __launch_bounds__(256) void diff_hgemm_kernel(
    const __half* __restrict__ P, const __half* __restrict__ Hin,
    __half* __restrict__ Z)
{
    constexpr int WN = BN / 2;
    constexpr int NT = WN / 8;

    __shared__ uint32_t As2[2][128][20];
    __shared__ uint32_t Bs2[2][16][BN + 8];

    const int tid  = threadIdx.x;
    const int lane = tid & 31;
    const int w    = tid >> 5;
    const int wm   = w & 3;
    const int wn   = w >> 2;
    const int lr   = lane >> 2;
    const int lc   = lane & 3;
    const int b    = blockIdx.z;
    const int i0   = blockIdx.x << 7;
    const size_t pb = (size_t)b * NN2;
    const size_t hb = (size_t)b * NNODE * BN;

    const int sa_r   = tid >> 1;
    const int sa_k16 = (tid & 1) << 4;

    uint4 pa0, pa1;
    uint4 bu0, bu1;      // BN==64 uses only .x/.y

#define DIFF_LDG(j0)                                                           \
    {                                                                          \
        const __half* p = P + pb + (size_t)(i0 + sa_r) * NNODE + (j0) + sa_k16;\
        pa0 = *reinterpret_cast<const uint4*>(p);                              \
        pa1 = *reinterpret_cast<const uint4*>(p + 8);                          \
        if (BN == 128) {                                                       \
            int k2r = tid >> 4, nh = (tid & 15) * 8;                           \
            const __half* q = Hin + hb + (size_t)((j0) + 2*k2r) * BN + nh;     \
            bu0 = *reinterpret_cast<const uint4*>(q);                          \
            bu1 = *reinterpret_cast<const uint4*>(q + BN);                     \
        } else {                                                               \
            int k2r = tid >> 4, nh = (tid & 15) * 4;                           \
            const __half* q = Hin + hb + (size_t)((j0) + 2*k2r) * BN + nh;     \
            uint2 t0 = *reinterpret_cast<const uint2*>(q);                     \
            uint2 t1 = *reinterpret_cast<const uint2*>(q + BN);                \
            bu0.x = t0.x; bu0.y = t0.y; bu1.x = t1.x; bu1.y = t1.y;            \
        }                                                                      \
    }

#define DIFF_STS(bufi)                                                        \
    {                                                                          \
        *reinterpret_cast<uint4*>(&As2[bufi][sa_r][(sa_k16>>1)    ]) = pa0;    \
        *reinterpret_cast<uint4*>(&As2[bufi][sa_r][(sa_k16>>1) + 4]) = pa1;    \
        if (BN == 128) {                                                       \
            int k2r = tid >> 4, nh = (tid & 15) * 8;                           \
            uint4 v0, v1;                                                      \
            v0.x = __byte_perm(bu0.x, bu1.x, 0x5410);                          \
            v0.y = __byte_perm(bu0.x, bu1.x, 0x7632);                          \
            v0.z = __byte_perm(bu0.y, bu1.y, 0x5410);                          \
            v0.w = __byte_perm(bu0.y, bu1.y, 0x7632);                          \
            v1.x = __byte_perm(bu0.z, bu1.z, 0x5410);                          \
            v1.y = __byte_perm(bu0.z, bu1.z, 0x7632);                          \
            v1.z = __byte_perm(bu0.w, bu1.w, 0x5410);                          \
            v1.w = __byte_perm(bu0.w, bu1.w, 0x7632);                          \
            *reinterpret_cast<uint4*>(&Bs2[bufi][k2r][nh    ]) = v0;           \
            *reinterpret_cast<uint4*>(&Bs2[bufi][k2r][nh + 4]) = v1;           \
        } else {                                                               \
            int k2r = tid >> 4, nh = (tid & 15) * 4;                           \
            uint4 v0;                                                          \
            v0.x = __byte_perm(bu0.x, bu1.x, 0x5410);                          \
            v0.y = __byte_perm(bu0.x, bu1.x, 0x7632);                          \
            v0.z = __byte_perm(bu0.y, bu1.y, 0x5410);                          \
            v0.w = __byte_perm(bu0.y, bu1.y, 0x7632);                          \
            *reinterpret_cast<uint4*>(&Bs2[bufi][k2r][nh]) = v0;               \
        }                                                                      \
    }

    float acc[2][NT][4];
#pragma unroll
    for (int mt = 0; mt < 2; ++mt)
#pragma unroll
        for (int nt = 0; nt < NT; ++nt)
#pragma unroll
            for (int i = 0; i < 4; ++i) acc[mt][nt][i] = 0.f;

    DIFF_LDG(0);
    DIFF_STS(0);
    __syncthreads();

    int buf = 0;
    for (int j0 = 0; j0 < NNODE; j0 += 32) {
        const bool has_next = (j0 + 32 < NNODE);
        if (has_next) DIFF_LDG(j0 + 32);

#pragma unroll
        for (int s = 0; s < 2; ++s) {
            uint32_t a[2][4], bf[NT][2];
#pragma unroll
            for (int mt = 0; mt < 2; ++mt) {
                int rm = wm*32 + mt*16 + lr;
                a[mt][0] = As2[buf][rm    ][s*8 + lc    ];
                a[mt][1] = As2[buf][rm + 8][s*8 + lc    ];
                a[mt][2] = As2[buf][rm    ][s*8 + lc + 4];
                a[mt][3] = As2[buf][rm + 8][s*8 + lc + 4];
            }
#pragma unroll
            for (int nt = 0; nt < NT; ++nt) {
                int nb = wn*WN + nt*8 + lr;
                bf[nt][0] = Bs2[buf][s*8 + lc    ][nb];
                bf[nt][1] = Bs2[buf][s*8 + lc + 4][nb];
            }
#pragma unroll
            for (int mt = 0; mt < 2; ++mt)
#pragma unroll
                for (int nt = 0; nt < NT; ++nt)
                    mma_f16(acc[mt][nt], a[mt], bf[nt], acc[mt][nt]);
        }

        if (has_next) DIFF_STS(buf ^ 1);
        __syncthreads();
        buf ^= 1;
    }

#pragma unroll
    for (int mt = 0; mt < 2; ++mt) {
#pragma unroll
        for (int nt = 0; nt < NT; ++nt) {
            int col = wn*WN + nt*8 + 2*lc;
#pragma unroll
            for (int half = 0; half < 2; ++half) {
                int row = i0 + wm*32 + mt*16 + lr + half*8;
                *reinterpret_cast<uint32_t*>(Z + hb + (size_t)row * BN + col) =
                    f2h2(acc[mt][nt][half*2+0], acc[mt][nt][half*2+1]);
            }
        }
    }
#undef DIFF_LDG
#undef DIFF_STS
}

// ========== fp16 flash attention: H=2 heads, d=64, N=1024 ==========
__global__ __launch_bounds__(256) void attn_mma_kernel(
    const __half* __restrict__ Qg, const __half* __restrict__ Kg,
    const __half* __restrict__ Vg, __half* __restrict__ Og)
{
    __shared__ uint32_t Ps2[128][36];   // Q staging, then P (warp-local)
    __shared__ uint32_t Ks2[64][36];
    __shared__ uint32_t Vs2[32][72];

    const int tid  = threadIdx.x;
    const int lane = tid & 31;
    const int w    = tid >> 5;
    const int lr   = lane >> 2;
    const int lc   = lane & 3;
    const int b    = blockIdx.z, h = blockIdx.y;
    const int q0   = blockIdx.x << 7;
    const size_t rb = (size_t)b * NNODE;
    const int hoff = h * 64;
    const float SC = 0.125f * 1.4426950408889634f;
    const __half2 h2sc = __float2half2_rn(SC);

    // --- stage this warp's Q rows (scaled); 32 halves per thread = 4 x uint4 ---
    {
        int r   = w*16 + (lane >> 1);
        int seg = (lane & 1) * 32;                 // halves
        const __half* p = Qg + (rb + q0 + r) * 128 + hoff + seg;
#pragma unroll
        for (int jj = 0; jj < 4; ++jj) {
            uint4 u = *reinterpret_cast<const uint4*>(p + 8*jj);
            __half2* hu = reinterpret_cast<__half2*>(&u);
#pragma unroll
            for (int q = 0; q < 4; ++q) hu[q] = __hmul2(hu[q], h2sc);
            *reinterpret_cast<uint4*>(&Ps2[r][(seg>>1) + 4*jj]) = u;
        }
    }
    __syncwarp();

    uint32_t qa[4][4];
#pragma unroll
    for (int ks = 0; ks < 4; ++ks) {
        qa[ks][0] = Ps2[w*16 + lr    ][ks*8 + lc    ];
        qa[ks][1] = Ps2[w*16 + lr + 8][ks*8 + lc    ];
        qa[ks][2] = Ps2[w*16 + lr    ][ks*8 + lc + 4];
        qa[ks][3] = Ps2[w*16 + lr + 8][ks*8 + lc + 4];
    }

    float m0 = -1e30f, m1 = -1e30f, l0 = 0.f, l1 = 0.f;
    float oacc[8][4];
#pragma unroll
    for (int nt = 0; nt < 8; ++nt)
#pragma unroll
        for (int i = 0; i < 4; ++i) oacc[nt][i] = 0.f;

    uint4 pk0, pk1, uv0, uv1;
    const int kr   = tid >> 2;
    const int kseg = (tid & 3) << 4;
    const int vk2r = tid >> 3;
    const int vdq  = (tid & 7) * 8;

#define ATTN_LDG(j0)                                                           \
    {                                                                          \
        const __half* p = Kg + (rb + (j0) + kr) * 128 + hoff + kseg;           \
        pk0 = *reinterpret_cast<const uint4*>(p);                              \
        pk1 = *reinterpret_cast<const uint4*>(p + 8);                          \
        const __half* q = Vg + (rb + (j0) + 2*vk2r) * 128 + hoff + vdq;        \
        uv0 = *reinterpret_cast<const uint4*>(q);                              \
        uv1 = *reinterpret_cast<const uint4*>(q + 128);                        \
    }

#define ATTN_STS()                                                            \
    {                                                                          \
        *reinterpret_cast<uint4*>(&Ks2[kr][(kseg>>1)    ]) = pk0;              \
        *reinterpret_cast<uint4*>(&Ks2[kr][(kseg>>1) + 4]) = pk1;              \
        uint4 v0, v1;                                                          \
        v0.x = __byte_perm(uv0.x, uv1.x, 0x5410);                              \
        v0.y = __byte_perm(uv0.x, uv1.x, 0x7632);                              \
        v0.z = __byte_perm(uv0.y, uv1.y, 0x5410);                              \
        v0.w = __byte_perm(uv0.y, uv1.y, 0x7632);                              \
        v1.x = __byte_perm(uv0.z, uv1.z, 0x5410);                              \
        v1.y = __byte_perm(uv0.z, uv1.z, 0x7632);                              \
        v1.z = __byte_perm(uv0.w, uv1.w, 0x5410);                              \
        v1.w = __byte_perm(uv0.w, uv1.w, 0x7632);                              \
        *reinterpret_cast<uint4*>(&Vs2[vk2r][vdq    ]) = v0;                   \
        *reinterpret_cast<uint4*>(&Vs2[vk2r][vdq + 4]) = v1;                   \
    }

    ATTN_LDG(0);
    ATTN_STS();
    __syncthreads();

    for (int c = 0; c < NNODE/64; ++c) {
        float sacc[8][4];
#pragma unroll
        for (int nt = 0; nt < 8; ++nt)
#pragma unroll
            for (int i = 0; i < 4; ++i) sacc[nt][i] = 0.f;
#pragma unroll
        for (int ks = 0; ks < 4; ++ks) {
#pragma unroll
            for (int nt = 0; nt < 8; ++nt) {
                uint32_t bf[2];
                bf[0] = Ks2[nt*8 + lr][ks*8 + lc    ];
                bf[1] = Ks2[nt*8 + lr][ks*8 + lc + 4];
                mma_f16(sacc[nt], qa[ks], bf, sacc[nt]);
            }
        }

        const bool has_next = (c + 1 < NNODE/64);
        if (has_next) ATTN_LDG((c + 1) * 64);

        float rmax0 = -1e30f, rmax1 = -1e30f;
#pragma unroll
        for (int nt = 0; nt < 8; ++nt) {
            rmax0 = fmaxf(rmax0, fmaxf(sacc[nt][0], sacc[nt][1]));
            rmax1 = fmaxf(rmax1, fmaxf(sacc[nt][2], sacc[nt][3]));
        }
        rmax0 = fmaxf(rmax0, __shfl_xor_sync(0xffffffffu, rmax0, 1));
        rmax0 = fmaxf(rmax0, __shfl_xor_sync(0xffffffffu, rmax0, 2));
        rmax1 = fmaxf(rmax1, __shfl_xor_sync(0xffffffffu, rmax1, 1));
        rmax1 = fmaxf(rmax1, __shfl_xor_sync(0xffffffffu, rmax1, 2));

        float mn0 = fmaxf(m0, rmax0), mn1 = fmaxf(m1, rmax1);
        float cr0 = exp2f(m0 - mn0), cr1 = exp2f(m1 - mn1);
        m0 = mn0; m1 = mn1;

        float rs0 = 0.f, rs1 = 0.f;
#pragma unroll
        for (int nt = 0; nt < 8; ++nt) {
            float p00 = exp2f(sacc[nt][0] - mn0);
            float p01 = exp2f(sacc[nt][1] - mn0);
            float p10 = exp2f(sacc[nt][2] - mn1);
            float p11 = exp2f(sacc[nt][3] - mn1);
            __half2 h0 = __floats2half2_rn(p00, p01);
            __half2 h1 = __floats2half2_rn(p10, p11);
            float2 f0 = __half22float2(h0);
            float2 f1 = __half22float2(h1);
            rs0 += f0.x + f0.y;
            rs1 += f1.x + f1.y;
            Ps2[w*16 + lr    ][nt*4 + lc] = h2bits(h0);
            Ps2[w*16 + lr + 8][nt*4 + lc] = h2bits(h1);
        }
        rs0 += __shfl_xor_sync(0xffffffffu, rs0, 1);
        rs0 += __shfl_xor_sync(0xffffffffu, rs0, 2);
        rs1 += __shfl_xor_sync(0xffffffffu, rs1, 1);
        rs1 += __shfl_xor_sync(0xffffffffu, rs1, 2);
        l0 = l0 * cr0 + rs0;
        l1 = l1 * cr1 + rs1;

#pragma unroll
        for (int nt = 0; nt < 8; ++nt) {
            oacc[nt][0] *= cr0; oacc[nt][1] *= cr0;
            oacc[nt][2] *= cr1; oacc[nt][3] *= cr1;
        }
        __syncwarp();

#pragma unroll
        for (int ks = 0; ks < 4; ++ks) {
            uint32_t pa[4];
            pa[0] = Ps2[w*16 + lr    ][ks*8 + lc    ];
            pa[1] = Ps2[w*16 + lr + 8][ks*8 + lc    ];
            pa[2] = Ps2[w*16 + lr    ][ks*8 + lc + 4];
            pa[3] = Ps2[w*16 + lr + 8][ks*8 + lc + 4];
#pragma unroll
            for (int nt = 0; nt < 8; ++nt) {
                uint32_t bf[2];
                bf[0] = Vs2[ks*8 + lc    ][nt*8 + lr];
                bf[1] = Vs2[ks*8 + lc + 4][nt*8 + lr];
                mma_f16(oacc[nt], pa, bf, oacc[nt]);
            }
        }

        __syncthreads();
        if (has_next) {
            ATTN_STS();
            __syncthreads();
        }
    }

    float inv0 = 1.f / l0, inv1 = 1.f / l1;
#pragma unroll
    for (int nt = 0; nt < 8; ++nt) {
        int col = hoff + nt*8 + 2*lc;
        *reinterpret_cast<uint32_t*>(Og + (rb + q0 + w*16 + lr    ) * 128 + col) =
            f2h2(oacc[nt][0] * inv0, oacc[nt][1] * inv0);
        *reinterpret_cast<uint32_t*>(Og + (rb + q0 + w*16 + lr + 8) * 128 + col) =
            f2h2(oacc[nt][2] * inv1, oacc[nt][3] * inv1);
    }
#undef ATTN_LDG
#undef ATTN_STS
}

// ---------------- final classifier: out = hp16 @ W_fin + b_fin ----------------
__global__ __launch_bounds__(256) void final_kernel(
    const __half* __restrict__ hp, const float* __restrict__ W,
    const float* __restrict__ bias, float* __restrict__ out)
{
    __shared__ float Ws[256];
    __shared__ float bs[2];
    if (threadIdx.x < 256) Ws[threadIdx.x] = W[threadIdx.x];
    if (threadIdx.x < 2)   bs[threadIdx.x] = bias[threadIdx.x];
    __syncthreads();
    size_t row = (size_t)blockIdx.x * blockDim.x + threadIdx.x;
    const __half2* hr = reinterpret_cast<const __half2*>(hp + row * 128);
    float a0 = bs[0], a1 = bs[1];
#pragma unroll
    for (int k2 = 0; k2 < 64; ++k2) {
        float2 f = __half22float2(hr[k2]);
        a0 += f.x * Ws[4*k2+0] + f.y * Ws[4*k2+2];
        a1 += f.x * Ws[4*k2+1] + f.y * Ws[4*k2+3];
    }
    out[row*2+0] = a0;
    out[row*2+1] = a1;
}

// ---------------- launch ----------------
extern "C" void kernel_launch(void* const* d_in, const int* in_sizes, int n_in,
                              void* d_out, int out_size) {
    const float* X     = (const float*)d_in[0];
    const float* A     = (const float*)d_in[1];
    const float* T     = (const float*)d_in[2];
    const float* theta = (const float*)d_in[3];
    const float* W_raw = (const float*)d_in[4];
    const float* b_raw = (const float*)d_in[5];
    const float* Wd0   = (const float*)d_in[6];
    const float* bd0   = (const float*)d_in[7];
    const float* Wd1   = (const float*)d_in[8];
    const float* bd1   = (const float*)d_in[9];
    const float* W_fin = (const float*)d_in[10];
    const float* b_fin = (const float*)d_in[11];
    const float* Wq0 = (const float*)d_in[12]; const float* bq0 = (const float*)d_in[13];
    const float* Wk0 = (const float*)d_in[14]; const float* bk0 = (const float*)d_in[15];
    const float* Wv0 = (const float*)d_in[16]; const float* bv0 = (const float*)d_in[17];
    const float* Wo0 = (const float*)d_in[18]; const float* bo0 = (const float*)d_in[19];
    const float* Wq1 = (const float*)d_in[20]; const float* bq1 = (const float*)d_in[21];
    const float* Wk1 = (const float*)d_in[22]; const float* bk1 = (const float*)d_in[23];
    const float* Wv1 = (const float*)d_in[24]; const float* bv1 = (const float*)d_in[25];
    const float* Wo1 = (const float*)d_in[26]; const float* bo1 = (const float*)d_in[27];

    __half *P0, *P1, *X16, *hp, *h, *z, *qb, *kb, *vb, *ctx;
    cudaGetSymbolAddress((void**)&P0,  g_P0);
    cudaGetSymbolAddress((void**)&P1,  g_P1);
    cudaGetSymbolAddress((void**)&X16, g_X16);
    cudaGetSymbolAddress((void**)&hp,  g_hp);
    cudaGetSymbolAddress((void**)&h,   g_h);
    cudaGetSymbolAddress((void**)&z,   g_z);
    cudaGetSymbolAddress((void**)&qb,  g_qb);
    cudaGetSymbolAddress((void**)&kb,  g_kb);
    cudaGetSymbolAddress((void**)&vb,  g_vb);
    cudaGetSymbolAddress((void**)&ctx, g_ctx);

    const int ggrid = M_ROWS / 128;
    dim3 dgrid(NNODE / 128, 1, NB);
    dim3 attn_grid(NNODE / 128, 2, NB);

    theta_softmax_kernel<<<1, 32>>>(theta);
    qmix_kernel<<<2 * 1024 * 1024 / 256, 256>>>(T);
    pmul_kernel<<<NB * 1024 * 1024 / 1024, 256>>>(A);
    tohalf_kernel<<<M_ROWS * 64 / 1024, 256>>>(X, X16);

    // raw projection: hp = X @ W_raw + b_raw
    hgemm_kernel<<<ggrid, 256>>>(X16, X16, 64, 64, W_raw, b_raw, nullptr, hp, 0);

    // layer 0 diffusion
    diff_hgemm_kernel<64><<<dgrid, 256>>>(P0, X16, z);
    hgemm_kernel<<<ggrid, 256>>>(z, z, 64, 64, Wd0, bd0, nullptr, h, 1);

    // layer 0 attention
    hgemm_kernel<<<ggrid, 256>>>(h, hp, 128, 256, Wq0, bq0, nullptr, qb, 0);
    hgemm_kernel<<<ggrid, 256>>>(h, hp, 128, 256, Wk0, bk0, nullptr, kb, 0);
    hgemm_kernel<<<ggrid, 256>>>(h, hp, 128, 256, Wv0, bv0, nullptr, vb, 0);
    attn_mma_kernel<<<attn_grid, 256>>>(qb, kb, vb, ctx);
    hgemm_kernel<<<ggrid, 256>>>(ctx, ctx, 128, 128, Wo0, bo0, nullptr, hp, 1);

    // layer 1 diffusion
    diff_hgemm_kernel<128><<<dgrid, 256>>>(P1, h, z);
    hgemm_kernel<<<ggrid, 256>>>(z, z, 128, 128, Wd1, bd1, nullptr, h, 1);

    // layer 1 attention with residual
    hgemm_kernel<<<ggrid, 256>>>(h, hp, 128, 256, Wq1, bq1, nullptr, qb, 0);
    hgemm_kernel<<<ggrid, 256>>>(h, hp, 128, 256, Wk1, bk1, nullptr, kb, 0);
    hgemm_kernel<<<ggrid, 256>>>(h, hp, 128, 256, Wv1, bv1, nullptr, vb, 0);
    attn_mma_kernel<<<attn_grid, 256>>>(qb, kb, vb, ctx);
    hgemm_kernel<<<ggrid, 256>>>(ctx, ctx, 128, 128, Wo1, bo1, hp, hp, 1);

    // classifier
    final_kernel<<<M_ROWS / 256, 256>>>(hp, W_fin, b_fin, (float*)d_out);
}